// round 11
// baseline (speedup 1.0000x reference)
#include <cuda_runtime.h>
#include <cuda_bf16.h>
#include <stdint.h>
#include <math.h>

#define BATCH 8
#define CH    128
#define NPIX  4096
#define BR    128
#define BC    64
#define NT    (NPIX / BC)   // 64
#define JSPLIT 4
#define TILES_PER_UNIT (NT / JSPLIT)   // 16

// bf16 hi/lo split operands (emulated-fp32 MMA)
__device__ __align__(16) __nv_bfloat16 g_Qhi[BATCH * NPIX * CH];  // [b][n][c]
__device__ __align__(16) __nv_bfloat16 g_Qlo[BATCH * NPIX * CH];
__device__ __align__(16) __nv_bfloat16 g_Khi[BATCH * NPIX * CH];  // [b][n][c]
__device__ __align__(16) __nv_bfloat16 g_Klo[BATCH * NPIX * CH];
__device__ __align__(16) __nv_bfloat16 g_Vhi[BATCH * CH * NPIX];  // [b][c][n]
__device__ __align__(16) __nv_bfloat16 g_Vlo[BATCH * CH * NPIX];

// split-j partial outputs: [b][jc][iblk][i 128][c 128], and row sums
__device__ __align__(16) float g_O[BATCH * JSPLIT * 32 * 128 * 128];  // 64 MB
__device__ __align__(16) float g_L[BATCH * JSPLIT * 32 * 128];

typedef unsigned long long u64;

__device__ __forceinline__ uint32_t smem_u32(const void* p) {
    uint32_t a;
    asm("{ .reg .u64 t; cvta.to.shared.u64 t, %1; cvt.u32.u64 %0, t; }" : "=r"(a) : "l"(p));
    return a;
}
__device__ __forceinline__ void cpasync16(uint32_t dst, const void* src) {
    asm volatile("cp.async.cg.shared.global [%0], [%1], 16;" :: "r"(dst), "l"(src));
}
#define CP_COMMIT() asm volatile("cp.async.commit_group;" ::: "memory")
#define CP_WAIT0()  asm volatile("cp.async.wait_group 0;" ::: "memory")

// ---- packed f32x2 helpers ----
__device__ __forceinline__ void fma2(u64& d, u64 a, u64 b) {
    asm("fma.rn.f32x2 %0, %1, %2, %0;" : "+l"(d) : "l"(a), "l"(b));
}
__device__ __forceinline__ u64 pack2(float lo, float hi) {
    u64 d; asm("mov.b64 %0, {%1, %2};" : "=l"(d) : "f"(lo), "f"(hi)); return d;
}
__device__ __forceinline__ float2 unpack2(u64 a) {
    float2 r; asm("mov.b64 {%0, %1}, %2;" : "=f"(r.x), "=f"(r.y) : "l"(a)); return r;
}
__device__ __forceinline__ float ex2(float x) {
    float y; asm("ex2.approx.ftz.f32 %0, %1;" : "=f"(y) : "f"(x)); return y;
}

// m16n8k16 row.col bf16 -> fp32, D==C in place
__device__ __forceinline__ void mma16816(float* c,
    uint32_t a0, uint32_t a1, uint32_t a2, uint32_t a3, uint32_t b0, uint32_t b1) {
    asm volatile(
        "mma.sync.aligned.m16n8k16.row.col.f32.bf16.bf16.f32 "
        "{%0,%1,%2,%3}, {%4,%5,%6,%7}, {%8,%9}, {%0,%1,%2,%3};"
        : "+f"(c[0]), "+f"(c[1]), "+f"(c[2]), "+f"(c[3])
        : "r"(a0), "r"(a1), "r"(a2), "r"(a3), "r"(b0), "r"(b1));
}

// ldmatrix x4 non-trans
__device__ __forceinline__ void ldsm4(uint32_t& r0, uint32_t& r1, uint32_t& r2,
                                      uint32_t& r3, uint32_t addr) {
    asm volatile("ldmatrix.sync.aligned.m8n8.x4.shared.b16 {%0,%1,%2,%3}, [%4];"
                 : "=r"(r0), "=r"(r1), "=r"(r2), "=r"(r3) : "r"(addr));
}

// pack (pe,po) fp32 pair -> bf16x2 hi + bf16x2 lo (pe in low half)
__device__ __forceinline__ void splitP(float pe, float po, uint32_t& h, uint32_t& l) {
    uint32_t hh;
    asm("cvt.rn.bf16x2.f32 %0, %1, %2;" : "=r"(hh) : "f"(po), "f"(pe));
    __nv_bfloat162 hb = *reinterpret_cast<__nv_bfloat162*>(&hh);
    float2 hf = __bfloat1622float2(hb);
    uint32_t ll;
    asm("cvt.rn.bf16x2.f32 %0, %1, %2;" : "=r"(ll) : "f"(po - hf.y), "f"(pe - hf.x));
    h = hh; l = ll;
}
__device__ __forceinline__ void split2(float a, float b, uint32_t& hi, uint32_t& lo) {
    __nv_bfloat162 h = __floats2bfloat162_rn(a, b);
    float2 hf = __bfloat1622float2(h);
    __nv_bfloat162 l = __floats2bfloat162_rn(a - hf.x, b - hf.y);
    union { __nv_bfloat162 v; uint32_t u; } ch, cl;
    ch.v = h; cl.v = l;
    hi = ch.u; lo = cl.u;
}

// ====== QKV projection: 128o x 64p tiles, 2 CTAs/SM, f32x2 inner loop ======
// smem: Wt [128][132] fp32 (67584 B) + Xs [128][68] fp32 (34816 B) = 102400 B
#define PROJ_SMEM_FLOATS (CH * 132 + CH * 68)
#define LOG2E 1.4426950408889634f

__global__ void __launch_bounds__(256, 2) qkv_kernel(
    const float* __restrict__ x1, const float* __restrict__ x2,
    const float* __restrict__ Wq, const float* __restrict__ bq,
    const float* __restrict__ Wk, const float* __restrict__ bk,
    const float* __restrict__ Wv, const float* __restrict__ bv)
{
    extern __shared__ __align__(16) float sm[];
    float* Wt = sm;               // [128][132]
    float* Xs = sm + CH * 132;    // [128][68]  (also reused as T [64][132])

    const int t = threadIdx.x, tx = t & 15, ty = t >> 4;
    const int which = blockIdx.y, b = blockIdx.z, p0 = blockIdx.x * 64;

    const float* X    = (which == 0 ? x1 : x2) + (size_t)b * CH * NPIX;
    const float* W    = (which == 0 ? Wq : (which == 1 ? Wk : Wv));
    const float* bias = (which == 0 ? bq : (which == 1 ? bk : bv));

    // stage W transposed
#pragma unroll
    for (int it = 0; it < 8; ++it) {
        int oo = ty + 16 * it;
#pragma unroll
        for (int h = 0; h < 2; ++h) {
            int cc = 64 * h + 4 * tx;
            float4 w4 = *(const float4*)&W[oo * CH + cc];
            Wt[(cc + 0) * 132 + oo] = w4.x;
            Wt[(cc + 1) * 132 + oo] = w4.y;
            Wt[(cc + 2) * 132 + oo] = w4.z;
            Wt[(cc + 3) * 132 + oo] = w4.w;
        }
    }
    // stage X tile [128 c][64 p]
#pragma unroll
    for (int r = 0; r < 8; ++r) {
        int idx = t + 256 * r;            // 2048 float4 loads
        int cc = idx >> 4, pp = (idx & 15) * 4;
        *(float4*)&Xs[cc * 68 + pp] = *(const float4*)&X[(size_t)cc * NPIX + p0 + pp];
    }
    __syncthreads();

    u64 acc2[8][2];
#pragma unroll
    for (int i = 0; i < 8; ++i) { acc2[i][0] = 0ull; acc2[i][1] = 0ull; }

#pragma unroll 4
    for (int c = 0; c < CH; ++c) {
        float4 wa = *(const float4*)&Wt[c * 132 + 4 * ty];
        float4 wb = *(const float4*)&Wt[c * 132 + 64 + 4 * ty];
        ulonglong2 xa = *(const ulonglong2*)&Xs[c * 68 + 4 * tx];
        float wv[8] = {wa.x, wa.y, wa.z, wa.w, wb.x, wb.y, wb.z, wb.w};
#pragma unroll
        for (int i = 0; i < 8; ++i) {
            u64 w = pack2(wv[i], wv[i]);
            fma2(acc2[i][0], w, xa.x);
            fma2(acc2[i][1], w, xa.y);
        }
    }

    float acc[8][4];
#pragma unroll
    for (int i = 0; i < 8; ++i) {
        float2 v0 = unpack2(acc2[i][0]);
        float2 v1 = unpack2(acc2[i][1]);
        acc[i][0] = v0.x; acc[i][1] = v0.y; acc[i][2] = v1.x; acc[i][3] = v1.y;
    }

    if (which < 2) {
        const float qsc = (which == 0) ? LOG2E : 1.0f;
        __syncthreads();
        float* T = Xs;  // reuse: [p:64][132]
#pragma unroll
        for (int i = 0; i < 8; ++i) {
            int o = (i < 4) ? (4 * ty + i) : (64 + 4 * ty + i - 4);
            float bo = bias[o];
#pragma unroll
            for (int j = 0; j < 4; ++j)
                T[(4 * tx + j) * 132 + o] = (acc[i][j] + bo) * qsc;
        }
        __syncthreads();
        __nv_bfloat16* dHi = (which == 0 ? g_Qhi : g_Khi);
        __nv_bfloat16* dLo = (which == 0 ? g_Qlo : g_Klo);
        int p = t >> 2, h = t & 3;
        const float* src = T + p * 132 + 32 * h;
        size_t base = ((size_t)b * NPIX + p0 + p) * CH + 32 * h;
        uint32_t hi[16], lo[16];
#pragma unroll
        for (int m = 0; m < 16; ++m)
            split2(src[2 * m], src[2 * m + 1], hi[m], lo[m]);
        uint4* dh = (uint4*)(dHi + base);
        uint4* dl = (uint4*)(dLo + base);
#pragma unroll
        for (int k = 0; k < 4; ++k) {
            dh[k] = make_uint4(hi[4 * k], hi[4 * k + 1], hi[4 * k + 2], hi[4 * k + 3]);
            dl[k] = make_uint4(lo[4 * k], lo[4 * k + 1], lo[4 * k + 2], lo[4 * k + 3]);
        }
    } else {
#pragma unroll
        for (int i = 0; i < 8; ++i) {
            int o = (i < 4) ? (4 * ty + i) : (64 + 4 * ty + i - 4);
            float bo = bias[o];
            size_t rb = ((size_t)b * CH + o) * NPIX + p0 + 4 * tx;
            uint32_t h0, l0, h1, l1;
            split2(acc[i][0] + bo, acc[i][1] + bo, h0, l0);
            split2(acc[i][2] + bo, acc[i][3] + bo, h1, l1);
            *(uint2*)(g_Vhi + rb) = make_uint2(h0, h1);
            *(uint2*)(g_Vlo + rb) = make_uint2(l0, l1);
        }
    }
}

// ==== flash attention partial: HMMA bf16x3, ldmatrix, split-j (16 tiles/unit) ====
#define QHI_B 0
#define QLO_B 34816
#define BUF_B 69632
#define BUFSTRIDE 71680
#define KHI_B(d) (BUF_B + (d) * BUFSTRIDE)
#define VHI_B(d) (KHI_B(d) + 2 * 17408)
#define ATTN_SMEM_BYTES (BUF_B + 2 * BUFSTRIDE)   // 212992

__global__ void __launch_bounds__(256, 1) attn_kernel()
{
    extern __shared__ __align__(16) uint32_t sm32[];
    const uint32_t sb = smem_u32(sm32);

    const int t = threadIdx.x;
    const int wid = t >> 5;
    const int lane = t & 31;
    const int l7 = lane & 7;
    const int r8 = lane >> 3;
    const int iblk = blockIdx.x;
    const int jc   = blockIdx.y;
    const int b    = blockIdx.z;
    const int i0 = iblk * BR;
    const int jt0 = jc * TILES_PER_UNIT;

    // ---- stage Q hi/lo (persistent) + prefetch first tile via cp.async ----
    {
        const char* qh = (const char*)(g_Qhi + ((size_t)b * NPIX + i0) * CH);
        const char* ql = (const char*)(g_Qlo + ((size_t)b * NPIX + i0) * CH);
#pragma unroll
        for (int r = 0; r < 8; ++r) {
            int idx = t + 256 * r;
            int row = idx >> 4, off = idx & 15;
            cpasync16(sb + QHI_B + row * 272 + off * 16, qh + (size_t)idx * 16);
            cpasync16(sb + QLO_B + row * 272 + off * 16, ql + (size_t)idx * 16);
        }
        const int j0 = jt0 * BC;
        const char* kh = (const char*)(g_Khi + ((size_t)b * NPIX + j0) * CH);
        const char* kl = (const char*)(g_Klo + ((size_t)b * NPIX + j0) * CH);
        const char* vh = (const char*)(g_Vhi + (size_t)b * CH * NPIX + j0);
        const char* vl = (const char*)(g_Vlo + (size_t)b * CH * NPIX + j0);
#pragma unroll
        for (int r = 0; r < 4; ++r) {
            int idx = t + 256 * r;
            int row = idx >> 4, off = idx & 15;
            cpasync16(sb + KHI_B(0) + row * 272 + off * 16, kh + (size_t)idx * 16);
            cpasync16(sb + KHI_B(0) + 17408 + row * 272 + off * 16, kl + (size_t)idx * 16);
        }
#pragma unroll
        for (int r = 0; r < 4; ++r) {
            int idx = t + 256 * r;
            int row = idx >> 3, off = idx & 7;
            cpasync16(sb + VHI_B(0) + row * 144 + off * 16,
                      vh + (size_t)row * NPIX * 2 + off * 16);
            cpasync16(sb + VHI_B(0) + 18432 + row * 144 + off * 16,
                      vl + (size_t)row * NPIX * 2 + off * 16);
        }
        CP_COMMIT();
    }

    float o[16][4];
#pragma unroll
    for (int n = 0; n < 16; ++n)
#pragma unroll
        for (int r = 0; r < 4; ++r) o[n][r] = 0.f;
    float lsum0 = 0.f, lsum1 = 0.f;

    // ldmatrix per-lane addresses
    const uint32_t aOffH = sb + QHI_B
        + (uint32_t)(wid * 16 + l7 + (r8 & 1) * 8) * 272 + (uint32_t)((lane >> 4) & 1) * 16;
    const uint32_t aOffL = aOffH + (QLO_B - QHI_B);
    const uint32_t bRow = (uint32_t)((r8 >> 1) * 8 + l7);
    const uint32_t bOffK = bRow * 272 + (uint32_t)(r8 & 1) * 16;
    const uint32_t bOffV = bRow * 144 + (uint32_t)(r8 & 1) * 16;

    for (int jt = jt0; jt < jt0 + TILES_PER_UNIT; ++jt) {
        const int d = jt & 1;
        CP_WAIT0();
        __syncthreads();   // tile d ready; all warps past previous compute

        // prefetch next tile into other buffer (overlaps with this tile's compute)
        if (jt + 1 < jt0 + TILES_PER_UNIT) {
            const int j0n = (jt + 1) * BC, dn = (jt + 1) & 1;
            const char* kh = (const char*)(g_Khi + ((size_t)b * NPIX + j0n) * CH);
            const char* kl = (const char*)(g_Klo + ((size_t)b * NPIX + j0n) * CH);
            const char* vh = (const char*)(g_Vhi + (size_t)b * CH * NPIX + j0n);
            const char* vl = (const char*)(g_Vlo + (size_t)b * CH * NPIX + j0n);
#pragma unroll
            for (int r = 0; r < 4; ++r) {
                int idx = t + 256 * r;
                int row = idx >> 4, off = idx & 15;
                cpasync16(sb + KHI_B(dn) + row * 272 + off * 16, kh + (size_t)idx * 16);
                cpasync16(sb + KHI_B(dn) + 17408 + row * 272 + off * 16, kl + (size_t)idx * 16);
            }
#pragma unroll
            for (int r = 0; r < 4; ++r) {
                int idx = t + 256 * r;
                int row = idx >> 3, off = idx & 7;
                cpasync16(sb + VHI_B(dn) + row * 144 + off * 16,
                          vh + (size_t)row * NPIX * 2 + off * 16);
                cpasync16(sb + VHI_B(dn) + 18432 + row * 144 + off * 16,
                          vl + (size_t)row * NPIX * 2 + off * 16);
            }
            CP_COMMIT();
        }

        // ---- S = Q K^T (3-term bf16 emulated fp32), ldmatrix loads ----
        float s[8][4];
#pragma unroll
        for (int n = 0; n < 8; ++n)
#pragma unroll
            for (int r = 0; r < 4; ++r) s[n][r] = 0.f;

        const uint32_t kBase = sb + KHI_B(d) + bOffK;
#pragma unroll
        for (int kk = 0; kk < 8; ++kk) {
            uint32_t a0h, a1h, a2h, a3h, a0l, a1l, a2l, a3l;
            ldsm4(a0h, a1h, a2h, a3h, aOffH + kk * 32);
            ldsm4(a0l, a1l, a2l, a3l, aOffL + kk * 32);
#pragma unroll
            for (int np = 0; np < 4; ++np) {
                uint32_t b00, b01, b10, b11, c00, c01, c10, c11;
                ldsm4(b00, b01, b10, b11, kBase + np * 4352 + kk * 32);
                ldsm4(c00, c01, c10, c11, kBase + 17408 + np * 4352 + kk * 32);
                mma16816(s[2 * np],     a0h, a1h, a2h, a3h, b00, b01);
                mma16816(s[2 * np],     a0l, a1l, a2l, a3l, b00, b01);
                mma16816(s[2 * np],     a0h, a1h, a2h, a3h, c00, c01);
                mma16816(s[2 * np + 1], a0h, a1h, a2h, a3h, b10, b11);
                mma16816(s[2 * np + 1], a0l, a1l, a2l, a3l, b10, b11);
                mma16816(s[2 * np + 1], a0h, a1h, a2h, a3h, c10, c11);
            }
        }

        // ---- exp2 (no max; log2e folded into Q) + partial row sums ----
#pragma unroll
        for (int n = 0; n < 8; ++n) {
            s[n][0] = ex2(s[n][0]);
            s[n][1] = ex2(s[n][1]);
            s[n][2] = ex2(s[n][2]);
            s[n][3] = ex2(s[n][3]);
            lsum0 += s[n][0] + s[n][1];
            lsum1 += s[n][2] + s[n][3];
        }

        // ---- O += P V (3-term); P split in registers ----
        const uint32_t vBase = sb + VHI_B(d) + bOffV;
#pragma unroll
        for (int kk = 0; kk < 4; ++kk) {
            uint32_t pa0h, pa0l, pa1h, pa1l, pa2h, pa2l, pa3h, pa3l;
            splitP(s[2 * kk][0],     s[2 * kk][1],     pa0h, pa0l);
            splitP(s[2 * kk][2],     s[2 * kk][3],     pa1h, pa1l);
            splitP(s[2 * kk + 1][0], s[2 * kk + 1][1], pa2h, pa2l);
            splitP(s[2 * kk + 1][2], s[2 * kk + 1][3], pa3h, pa3l);
#pragma unroll
            for (int n2 = 0; n2 < 8; ++n2) {
                uint32_t b00, b01, b10, b11, c00, c01, c10, c11;
                ldsm4(b00, b01, b10, b11, vBase + n2 * 2304 + kk * 32);
                ldsm4(c00, c01, c10, c11, vBase + 18432 + n2 * 2304 + kk * 32);
                mma16816(o[2 * n2],     pa0h, pa1h, pa2h, pa3h, b00, b01);
                mma16816(o[2 * n2],     pa0l, pa1l, pa2l, pa3l, b00, b01);
                mma16816(o[2 * n2],     pa0h, pa1h, pa2h, pa3h, c00, c01);
                mma16816(o[2 * n2 + 1], pa0h, pa1h, pa2h, pa3h, b10, b11);
                mma16816(o[2 * n2 + 1], pa0l, pa1l, pa2l, pa3l, b10, b11);
                mma16816(o[2 * n2 + 1], pa0h, pa1h, pa2h, pa3h, c10, c11);
            }
        }
        __syncthreads();   // done reading tile d before it is overwritten
    }

    // ---- epilogue: store raw partial O and L (merge kernel normalizes) ----
    lsum0 += __shfl_xor_sync(0xffffffffu, lsum0, 1);
    lsum0 += __shfl_xor_sync(0xffffffffu, lsum0, 2);
    lsum1 += __shfl_xor_sync(0xffffffffu, lsum1, 1);
    lsum1 += __shfl_xor_sync(0xffffffffu, lsum1, 2);

    const size_t unit = ((size_t)(b * JSPLIT + jc) * 32 + iblk);
    float* Ob = g_O + unit * (128 * 128);
    float* Lb = g_L + unit * 128;
    const int g = lane >> 2, q = lane & 3;
    const int i = wid * 16 + g;
    if ((lane & 3) == 0) {
        Lb[i]     = lsum0;
        Lb[i + 8] = lsum1;
    }
#pragma unroll
    for (int n = 0; n < 16; ++n) {
        const int c = n * 8 + 2 * q;
        *(float2*)&Ob[(size_t)i * 128 + c]       = make_float2(o[n][0], o[n][1]);
        *(float2*)&Ob[(size_t)(i + 8) * 128 + c] = make_float2(o[n][2], o[n][3]);
    }
}

// ==== merge kernel: sum 4 j-chunk partials, normalize, transpose, store ====
#define MERGE_SMEM_BYTES (128 * 129 * 4 + 128 * 4)   // 66560

__global__ void __launch_bounds__(256, 1) merge_kernel(float* __restrict__ out)
{
    extern __shared__ __align__(16) float ms[];
    float* Os   = ms;               // [c:128][i:129]
    float* Linv = ms + 128 * 129;

    const int t = threadIdx.x;
    const int iblk = blockIdx.x;
    const int b    = blockIdx.y;

    const float* O0 = g_O + ((size_t)(b * JSPLIT) * 32 + iblk) * (128 * 128);
    const size_t sj = (size_t)32 * 128 * 128;

    if (t < 128) {
        const float* L0 = g_L + ((size_t)(b * JSPLIT) * 32 + iblk) * 128 + t;
        const size_t lj = (size_t)32 * 128;
        float L = L0[0] + L0[lj] + L0[2 * lj] + L0[3 * lj];
        Linv[t] = 1.f / L;
    }

#pragma unroll
    for (int r = 0; r < 16; ++r) {
        int idx = (r * 256 + t) * 4;
        int i = idx >> 7, c = idx & 127;
        float4 a  = *(const float4*)&O0[idx];
        float4 b2 = *(const float4*)&O0[sj + idx];
        float4 c4 = *(const float4*)&O0[2 * sj + idx];
        float4 d4 = *(const float4*)&O0[3 * sj + idx];
        Os[(c + 0) * 129 + i] = a.x + b2.x + c4.x + d4.x;
        Os[(c + 1) * 129 + i] = a.y + b2.y + c4.y + d4.y;
        Os[(c + 2) * 129 + i] = a.z + b2.z + c4.z + d4.z;
        Os[(c + 3) * 129 + i] = a.w + b2.w + c4.w + d4.w;
    }
    __syncthreads();

    const int c = t >> 1, h = t & 1;
    const float* src = Os + c * 129 + 64 * h;
    const float* li  = Linv + 64 * h;
    float* dst = out + ((size_t)b * CH + c) * NPIX + iblk * 128 + 64 * h;
#pragma unroll
    for (int k = 0; k < 16; ++k) {
        ((float4*)dst)[k] = make_float4(src[4 * k]     * li[4 * k],
                                        src[4 * k + 1] * li[4 * k + 1],
                                        src[4 * k + 2] * li[4 * k + 2],
                                        src[4 * k + 3] * li[4 * k + 3]);
    }
}

// ============================================================
extern "C" void kernel_launch(void* const* d_in, const int* in_sizes, int n_in,
                              void* d_out, int out_size)
{
    (void)in_sizes; (void)n_in; (void)out_size;
    const float* x1 = (const float*)d_in[0];
    const float* x2 = (const float*)d_in[1];
    const float* Wq = (const float*)d_in[2];
    const float* bq = (const float*)d_in[3];
    const float* Wk = (const float*)d_in[4];
    const float* bk = (const float*)d_in[5];
    const float* Wv = (const float*)d_in[6];
    const float* bv = (const float*)d_in[7];
    float* out = (float*)d_out;

    const int proj_smem = PROJ_SMEM_FLOATS * (int)sizeof(float);   // 102400
    cudaFuncSetAttribute(qkv_kernel, cudaFuncAttributeMaxDynamicSharedMemorySize, proj_smem);
    cudaFuncSetAttribute(attn_kernel, cudaFuncAttributeMaxDynamicSharedMemorySize, ATTN_SMEM_BYTES);
    cudaFuncSetAttribute(merge_kernel, cudaFuncAttributeMaxDynamicSharedMemorySize, MERGE_SMEM_BYTES);

    qkv_kernel<<<dim3(NPIX / 64, 3, BATCH), 256, proj_smem>>>(x1, x2, Wq, bq, Wk, bk, Wv, bv);
    attn_kernel<<<dim3(NPIX / BR, JSPLIT, BATCH), 256, ATTN_SMEM_BYTES>>>();
    merge_kernel<<<dim3(NPIX / 128, BATCH), 256, MERGE_SMEM_BYTES>>>(out);
}

// round 12
// speedup vs baseline: 1.0621x; 1.0621x over previous
#include <cuda_runtime.h>
#include <cuda_bf16.h>
#include <stdint.h>
#include <math.h>

#define BATCH 8
#define CH    128
#define NPIX  4096
#define BR    128
#define BC    64
#define NT    (NPIX / BC)   // 64
#define JSPLIT 4
#define TILES_PER_UNIT (NT / JSPLIT)   // 16

// bf16 hi/lo split operands (emulated-fp32 MMA)
__device__ __align__(16) __nv_bfloat16 g_Qhi[BATCH * NPIX * CH];  // [b][n][c]
__device__ __align__(16) __nv_bfloat16 g_Qlo[BATCH * NPIX * CH];
__device__ __align__(16) __nv_bfloat16 g_Khi[BATCH * NPIX * CH];  // [b][n][c]
__device__ __align__(16) __nv_bfloat16 g_Klo[BATCH * NPIX * CH];
__device__ __align__(16) __nv_bfloat16 g_Vhi[BATCH * CH * NPIX];  // [b][c][n]
__device__ __align__(16) __nv_bfloat16 g_Vlo[BATCH * CH * NPIX];

// split-j partial outputs: [b][jc][iblk][i 128][c 128], and row sums
__device__ __align__(16) float g_O[BATCH * JSPLIT * 32 * 128 * 128];  // 64 MB
__device__ __align__(16) float g_L[BATCH * JSPLIT * 32 * 128];

typedef unsigned long long u64;

__device__ __forceinline__ uint32_t smem_u32(const void* p) {
    uint32_t a;
    asm("{ .reg .u64 t; cvta.to.shared.u64 t, %1; cvt.u32.u64 %0, t; }" : "=r"(a) : "l"(p));
    return a;
}
__device__ __forceinline__ void cpasync16(uint32_t dst, const void* src) {
    asm volatile("cp.async.cg.shared.global [%0], [%1], 16;" :: "r"(dst), "l"(src));
}
#define CP_COMMIT() asm volatile("cp.async.commit_group;" ::: "memory")
#define CP_WAIT0()  asm volatile("cp.async.wait_group 0;" ::: "memory")

__device__ __forceinline__ float ex2(float x) {
    float y; asm("ex2.approx.ftz.f32 %0, %1;" : "=f"(y) : "f"(x)); return y;
}

// m16n8k16 row.col bf16 -> fp32, D==C in place
__device__ __forceinline__ void mma16816(float* c,
    uint32_t a0, uint32_t a1, uint32_t a2, uint32_t a3, uint32_t b0, uint32_t b1) {
    asm volatile(
        "mma.sync.aligned.m16n8k16.row.col.f32.bf16.bf16.f32 "
        "{%0,%1,%2,%3}, {%4,%5,%6,%7}, {%8,%9}, {%0,%1,%2,%3};"
        : "+f"(c[0]), "+f"(c[1]), "+f"(c[2]), "+f"(c[3])
        : "r"(a0), "r"(a1), "r"(a2), "r"(a3), "r"(b0), "r"(b1));
}

// ldmatrix x4 non-trans / trans
__device__ __forceinline__ void ldsm4(uint32_t& r0, uint32_t& r1, uint32_t& r2,
                                      uint32_t& r3, uint32_t addr) {
    asm volatile("ldmatrix.sync.aligned.m8n8.x4.shared.b16 {%0,%1,%2,%3}, [%4];"
                 : "=r"(r0), "=r"(r1), "=r"(r2), "=r"(r3) : "r"(addr));
}
__device__ __forceinline__ void ldsm4t(uint32_t& r0, uint32_t& r1, uint32_t& r2,
                                       uint32_t& r3, uint32_t addr) {
    asm volatile("ldmatrix.sync.aligned.m8n8.x4.trans.shared.b16 {%0,%1,%2,%3}, [%4];"
                 : "=r"(r0), "=r"(r1), "=r"(r2), "=r"(r3) : "r"(addr));
}

// pack (pe,po) fp32 pair -> bf16x2 hi + bf16x2 lo (pe in low half)
__device__ __forceinline__ void splitP(float pe, float po, uint32_t& h, uint32_t& l) {
    uint32_t hh;
    asm("cvt.rn.bf16x2.f32 %0, %1, %2;" : "=r"(hh) : "f"(po), "f"(pe));
    __nv_bfloat162 hb = *reinterpret_cast<__nv_bfloat162*>(&hh);
    float2 hf = __bfloat1622float2(hb);
    uint32_t ll;
    asm("cvt.rn.bf16x2.f32 %0, %1, %2;" : "=r"(ll) : "f"(po - hf.y), "f"(pe - hf.x));
    h = hh; l = ll;
}
__device__ __forceinline__ void split2(float a, float b, uint32_t& hi, uint32_t& lo) {
    __nv_bfloat162 h = __floats2bfloat162_rn(a, b);
    float2 hf = __bfloat1622float2(h);
    __nv_bfloat162 l = __floats2bfloat162_rn(a - hf.x, b - hf.y);
    union { __nv_bfloat162 v; uint32_t u; } ch, cl;
    ch.v = h; cl.v = l;
    hi = ch.u; lo = cl.u;
}

#define LOG2E 1.4426950408889634f

// ====== QKV projection on HMMA bf16x3: Out[o,p] = W[o,c] X[c,p] ======
// smem: Whi[128o][136c] 34816 | Wlo 34816 | Xhi[128c][136p] 34816 | Xlo 34816
#define WHI_B 0
#define WLO_B 34816
#define XHI_B 69632
#define XLO_B 104448
#define PROJ_SMEM_BYTES 139264

__global__ void __launch_bounds__(256, 1) qkv_kernel(
    const float* __restrict__ x1, const float* __restrict__ x2,
    const float* __restrict__ Wq, const float* __restrict__ bq,
    const float* __restrict__ Wk, const float* __restrict__ bk,
    const float* __restrict__ Wv, const float* __restrict__ bv)
{
    extern __shared__ __align__(16) char smc[];
    const uint32_t sb = smem_u32(smc);

    const int t = threadIdx.x;
    const int wid = t >> 5;
    const int lane = t & 31;
    const int l7 = lane & 7;
    const int r8 = lane >> 3;
    const int which = blockIdx.y, b = blockIdx.z, p0 = blockIdx.x * 128;

    const float* X    = (which == 0 ? x1 : x2) + (size_t)b * CH * NPIX;
    const float* W    = (which == 0 ? Wq : (which == 1 ? Wk : Wv));
    const float* bias = (which == 0 ? bq : (which == 1 ? bk : bv));

    // ---- stage W hi/lo: [o][c+pad] bf16 ----
#pragma unroll
    for (int r = 0; r < 4; ++r) {
        int task = t + 256 * r;            // 1024 tasks, each 16 c-values
        int o = task >> 3, c16 = (task & 7) * 16;
        const float4* ws = (const float4*)&W[o * CH + c16];
        uint32_t hi[8], lo[8];
#pragma unroll
        for (int j = 0; j < 4; ++j) {
            float4 w4 = ws[j];
            split2(w4.x, w4.y, hi[2 * j], lo[2 * j]);
            split2(w4.z, w4.w, hi[2 * j + 1], lo[2 * j + 1]);
        }
        char* dh = smc + WHI_B + o * 272 + c16 * 2;
        char* dl = smc + WLO_B + o * 272 + c16 * 2;
        ((uint4*)dh)[0] = make_uint4(hi[0], hi[1], hi[2], hi[3]);
        ((uint4*)dh)[1] = make_uint4(hi[4], hi[5], hi[6], hi[7]);
        ((uint4*)dl)[0] = make_uint4(lo[0], lo[1], lo[2], lo[3]);
        ((uint4*)dl)[1] = make_uint4(lo[4], lo[5], lo[6], lo[7]);
    }
    // ---- stage X tile hi/lo: [c][p+pad] bf16 (natural orientation) ----
#pragma unroll
    for (int r = 0; r < 16; ++r) {
        int idx = t + 256 * r;             // 4096 float4 loads
        int c = idx >> 5, p4 = (idx & 31) * 4;
        float4 x4 = *(const float4*)&X[(size_t)c * NPIX + p0 + p4];
        uint32_t h0, l0, h1, l1;
        split2(x4.x, x4.y, h0, l0);
        split2(x4.z, x4.w, h1, l1);
        *(uint2*)(smc + XHI_B + c * 272 + p4 * 2) = make_uint2(h0, h1);
        *(uint2*)(smc + XLO_B + c * 272 + p4 * 2) = make_uint2(l0, l1);
    }
    __syncthreads();

    // ---- GEMM: warp w covers o rows [w*16, w*16+16), all 128 p ----
    float acc[16][4];
#pragma unroll
    for (int n = 0; n < 16; ++n)
#pragma unroll
        for (int r = 0; r < 4; ++r) acc[n][r] = 0.f;

    // A (W): non-trans ldsm, rows o, k=c contiguous
    const uint32_t aH = sb + WHI_B
        + (uint32_t)(wid * 16 + l7 + (r8 & 1) * 8) * 272 + (uint32_t)((lane >> 4) & 1) * 16;
    const uint32_t aL = aH + (WLO_B - WHI_B);
    // B (X): trans ldsm on [c][p] storage -> frags [p][c]
    const uint32_t bT = sb + XHI_B
        + (uint32_t)((r8 & 1) * 8 + l7) * 272 + (uint32_t)(r8 >> 1) * 16;

#pragma unroll
    for (int kk = 0; kk < 8; ++kk) {
        uint32_t a0h, a1h, a2h, a3h, a0l, a1l, a2l, a3l;
        ldsm4(a0h, a1h, a2h, a3h, aH + kk * 32);
        ldsm4(a0l, a1l, a2l, a3l, aL + kk * 32);
        const uint32_t bk16 = bT + (uint32_t)kk * 16 * 272;
#pragma unroll
        for (int np = 0; np < 8; ++np) {
            uint32_t b00, b01, b10, b11, c00, c01, c10, c11;
            ldsm4t(b00, b01, b10, b11, bk16 + np * 32);
            ldsm4t(c00, c01, c10, c11, bk16 + (XLO_B - XHI_B) + np * 32);
            mma16816(acc[2 * np],     a0h, a1h, a2h, a3h, b00, b01);
            mma16816(acc[2 * np],     a0l, a1l, a2l, a3l, b00, b01);
            mma16816(acc[2 * np],     a0h, a1h, a2h, a3h, c00, c01);
            mma16816(acc[2 * np + 1], a0h, a1h, a2h, a3h, b10, b11);
            mma16816(acc[2 * np + 1], a0l, a1l, a2l, a3l, b10, b11);
            mma16816(acc[2 * np + 1], a0h, a1h, a2h, a3h, c10, c11);
        }
    }

    const int g = lane >> 2, q = lane & 3;
    if (which < 2) {
        // transpose to [p][o] through smem (reuse X area), then split to bf16
        const float qsc = (which == 0) ? LOG2E : 1.0f;
        __syncthreads();
        float* T = (float*)(smc + XHI_B);   // [p:128][132]
#pragma unroll
        for (int n = 0; n < 16; ++n) {
            const int p = n * 8 + 2 * q;
            const int o0 = wid * 16 + g;
            float bo0 = bias[o0], bo8 = bias[o0 + 8];
            T[(p    ) * 132 + o0]     = (acc[n][0] + bo0) * qsc;
            T[(p + 1) * 132 + o0]     = (acc[n][1] + bo0) * qsc;
            T[(p    ) * 132 + o0 + 8] = (acc[n][2] + bo8) * qsc;
            T[(p + 1) * 132 + o0 + 8] = (acc[n][3] + bo8) * qsc;
        }
        __syncthreads();
        __nv_bfloat16* dHi = (which == 0 ? g_Qhi : g_Khi);
        __nv_bfloat16* dLo = (which == 0 ? g_Qlo : g_Klo);
        int p = t >> 1, h = t & 1;
        const float* src = T + p * 132 + 64 * h;
        size_t base = ((size_t)b * NPIX + p0 + p) * CH + 64 * h;
        uint32_t hi[32], lo[32];
#pragma unroll
        for (int m = 0; m < 32; ++m)
            split2(src[2 * m], src[2 * m + 1], hi[m], lo[m]);
        uint4* dh = (uint4*)(dHi + base);
        uint4* dl = (uint4*)(dLo + base);
#pragma unroll
        for (int k = 0; k < 8; ++k) {
            dh[k] = make_uint4(hi[4 * k], hi[4 * k + 1], hi[4 * k + 2], hi[4 * k + 3]);
            dl[k] = make_uint4(lo[4 * k], lo[4 * k + 1], lo[4 * k + 2], lo[4 * k + 3]);
        }
    } else {
        // V: [o][p] = [c][n] directly
        const int o0 = wid * 16 + g;
        float bo0 = bias[o0], bo8 = bias[o0 + 8];
        size_t rb0 = ((size_t)b * CH + o0) * NPIX + p0;
        size_t rb8 = rb0 + (size_t)8 * NPIX;
#pragma unroll
        for (int n = 0; n < 16; ++n) {
            const int p = n * 8 + 2 * q;
            uint32_t h0, l0, h1, l1;
            split2(acc[n][0] + bo0, acc[n][1] + bo0, h0, l0);
            split2(acc[n][2] + bo8, acc[n][3] + bo8, h1, l1);
            *(uint32_t*)(g_Vhi + rb0 + p) = h0;
            *(uint32_t*)(g_Vlo + rb0 + p) = l0;
            *(uint32_t*)(g_Vhi + rb8 + p) = h1;
            *(uint32_t*)(g_Vlo + rb8 + p) = l1;
        }
    }
}

// ==== flash attention partial: HMMA bf16x3, ldmatrix, split-j (16 tiles/unit) ====
#define QHI_B 0
#define QLO_B 34816
#define BUF_B 69632
#define BUFSTRIDE 71680
#define KHI_B(d) (BUF_B + (d) * BUFSTRIDE)
#define VHI_B(d) (KHI_B(d) + 2 * 17408)
#define ATTN_SMEM_BYTES (BUF_B + 2 * BUFSTRIDE)   // 212992

__global__ void __launch_bounds__(256, 1) attn_kernel()
{
    extern __shared__ __align__(16) uint32_t sm32[];
    const uint32_t sb = smem_u32(sm32);

    const int t = threadIdx.x;
    const int wid = t >> 5;
    const int lane = t & 31;
    const int l7 = lane & 7;
    const int r8 = lane >> 3;
    const int iblk = blockIdx.x;
    const int jc   = blockIdx.y;
    const int b    = blockIdx.z;
    const int i0 = iblk * BR;
    const int jt0 = jc * TILES_PER_UNIT;

    // ---- stage Q hi/lo (persistent) + prefetch first tile via cp.async ----
    {
        const char* qh = (const char*)(g_Qhi + ((size_t)b * NPIX + i0) * CH);
        const char* ql = (const char*)(g_Qlo + ((size_t)b * NPIX + i0) * CH);
#pragma unroll
        for (int r = 0; r < 8; ++r) {
            int idx = t + 256 * r;
            int row = idx >> 4, off = idx & 15;
            cpasync16(sb + QHI_B + row * 272 + off * 16, qh + (size_t)idx * 16);
            cpasync16(sb + QLO_B + row * 272 + off * 16, ql + (size_t)idx * 16);
        }
        const int j0 = jt0 * BC;
        const char* kh = (const char*)(g_Khi + ((size_t)b * NPIX + j0) * CH);
        const char* kl = (const char*)(g_Klo + ((size_t)b * NPIX + j0) * CH);
        const char* vh = (const char*)(g_Vhi + (size_t)b * CH * NPIX + j0);
        const char* vl = (const char*)(g_Vlo + (size_t)b * CH * NPIX + j0);
#pragma unroll
        for (int r = 0; r < 4; ++r) {
            int idx = t + 256 * r;
            int row = idx >> 4, off = idx & 15;
            cpasync16(sb + KHI_B(0) + row * 272 + off * 16, kh + (size_t)idx * 16);
            cpasync16(sb + KHI_B(0) + 17408 + row * 272 + off * 16, kl + (size_t)idx * 16);
        }
#pragma unroll
        for (int r = 0; r < 4; ++r) {
            int idx = t + 256 * r;
            int row = idx >> 3, off = idx & 7;
            cpasync16(sb + VHI_B(0) + row * 144 + off * 16,
                      vh + (size_t)row * NPIX * 2 + off * 16);
            cpasync16(sb + VHI_B(0) + 18432 + row * 144 + off * 16,
                      vl + (size_t)row * NPIX * 2 + off * 16);
        }
        CP_COMMIT();
    }

    float o[16][4];
#pragma unroll
    for (int n = 0; n < 16; ++n)
#pragma unroll
        for (int r = 0; r < 4; ++r) o[n][r] = 0.f;
    float lsum0 = 0.f, lsum1 = 0.f;

    const uint32_t aOffH = sb + QHI_B
        + (uint32_t)(wid * 16 + l7 + (r8 & 1) * 8) * 272 + (uint32_t)((lane >> 4) & 1) * 16;
    const uint32_t aOffL = aOffH + (QLO_B - QHI_B);
    const uint32_t bRow = (uint32_t)((r8 >> 1) * 8 + l7);
    const uint32_t bOffK = bRow * 272 + (uint32_t)(r8 & 1) * 16;
    const uint32_t bOffV = bRow * 144 + (uint32_t)(r8 & 1) * 16;

    for (int jt = jt0; jt < jt0 + TILES_PER_UNIT; ++jt) {
        const int d = jt & 1;
        CP_WAIT0();
        __syncthreads();

        if (jt + 1 < jt0 + TILES_PER_UNIT) {
            const int j0n = (jt + 1) * BC, dn = (jt + 1) & 1;
            const char* kh = (const char*)(g_Khi + ((size_t)b * NPIX + j0n) * CH);
            const char* kl = (const char*)(g_Klo + ((size_t)b * NPIX + j0n) * CH);
            const char* vh = (const char*)(g_Vhi + (size_t)b * CH * NPIX + j0n);
            const char* vl = (const char*)(g_Vlo + (size_t)b * CH * NPIX + j0n);
#pragma unroll
            for (int r = 0; r < 4; ++r) {
                int idx = t + 256 * r;
                int row = idx >> 4, off = idx & 15;
                cpasync16(sb + KHI_B(dn) + row * 272 + off * 16, kh + (size_t)idx * 16);
                cpasync16(sb + KHI_B(dn) + 17408 + row * 272 + off * 16, kl + (size_t)idx * 16);
            }
#pragma unroll
            for (int r = 0; r < 4; ++r) {
                int idx = t + 256 * r;
                int row = idx >> 3, off = idx & 7;
                cpasync16(sb + VHI_B(dn) + row * 144 + off * 16,
                          vh + (size_t)row * NPIX * 2 + off * 16);
                cpasync16(sb + VHI_B(dn) + 18432 + row * 144 + off * 16,
                          vl + (size_t)row * NPIX * 2 + off * 16);
            }
            CP_COMMIT();
        }

        float s[8][4];
#pragma unroll
        for (int n = 0; n < 8; ++n)
#pragma unroll
            for (int r = 0; r < 4; ++r) s[n][r] = 0.f;

        const uint32_t kBase = sb + KHI_B(d) + bOffK;
#pragma unroll
        for (int kk = 0; kk < 8; ++kk) {
            uint32_t a0h, a1h, a2h, a3h, a0l, a1l, a2l, a3l;
            ldsm4(a0h, a1h, a2h, a3h, aOffH + kk * 32);
            ldsm4(a0l, a1l, a2l, a3l, aOffL + kk * 32);
#pragma unroll
            for (int np = 0; np < 4; ++np) {
                uint32_t b00, b01, b10, b11, c00, c01, c10, c11;
                ldsm4(b00, b01, b10, b11, kBase + np * 4352 + kk * 32);
                ldsm4(c00, c01, c10, c11, kBase + 17408 + np * 4352 + kk * 32);
                mma16816(s[2 * np],     a0h, a1h, a2h, a3h, b00, b01);
                mma16816(s[2 * np],     a0l, a1l, a2l, a3l, b00, b01);
                mma16816(s[2 * np],     a0h, a1h, a2h, a3h, c00, c01);
                mma16816(s[2 * np + 1], a0h, a1h, a2h, a3h, b10, b11);
                mma16816(s[2 * np + 1], a0l, a1l, a2l, a3l, b10, b11);
                mma16816(s[2 * np + 1], a0h, a1h, a2h, a3h, c10, c11);
            }
        }

#pragma unroll
        for (int n = 0; n < 8; ++n) {
            s[n][0] = ex2(s[n][0]);
            s[n][1] = ex2(s[n][1]);
            s[n][2] = ex2(s[n][2]);
            s[n][3] = ex2(s[n][3]);
            lsum0 += s[n][0] + s[n][1];
            lsum1 += s[n][2] + s[n][3];
        }

        const uint32_t vBase = sb + VHI_B(d) + bOffV;
#pragma unroll
        for (int kk = 0; kk < 4; ++kk) {
            uint32_t pa0h, pa0l, pa1h, pa1l, pa2h, pa2l, pa3h, pa3l;
            splitP(s[2 * kk][0],     s[2 * kk][1],     pa0h, pa0l);
            splitP(s[2 * kk][2],     s[2 * kk][3],     pa1h, pa1l);
            splitP(s[2 * kk + 1][0], s[2 * kk + 1][1], pa2h, pa2l);
            splitP(s[2 * kk + 1][2], s[2 * kk + 1][3], pa3h, pa3l);
#pragma unroll
            for (int n2 = 0; n2 < 8; ++n2) {
                uint32_t b00, b01, b10, b11, c00, c01, c10, c11;
                ldsm4(b00, b01, b10, b11, vBase + n2 * 2304 + kk * 32);
                ldsm4(c00, c01, c10, c11, vBase + 18432 + n2 * 2304 + kk * 32);
                mma16816(o[2 * n2],     pa0h, pa1h, pa2h, pa3h, b00, b01);
                mma16816(o[2 * n2],     pa0l, pa1l, pa2l, pa3l, b00, b01);
                mma16816(o[2 * n2],     pa0h, pa1h, pa2h, pa3h, c00, c01);
                mma16816(o[2 * n2 + 1], pa0h, pa1h, pa2h, pa3h, b10, b11);
                mma16816(o[2 * n2 + 1], pa0l, pa1l, pa2l, pa3l, b10, b11);
                mma16816(o[2 * n2 + 1], pa0h, pa1h, pa2h, pa3h, c10, c11);
            }
        }
        __syncthreads();
    }

    lsum0 += __shfl_xor_sync(0xffffffffu, lsum0, 1);
    lsum0 += __shfl_xor_sync(0xffffffffu, lsum0, 2);
    lsum1 += __shfl_xor_sync(0xffffffffu, lsum1, 1);
    lsum1 += __shfl_xor_sync(0xffffffffu, lsum1, 2);

    const size_t unit = ((size_t)(b * JSPLIT + jc) * 32 + iblk);
    float* Ob = g_O + unit * (128 * 128);
    float* Lb = g_L + unit * 128;
    const int g = lane >> 2, q = lane & 3;
    const int i = wid * 16 + g;
    if ((lane & 3) == 0) {
        Lb[i]     = lsum0;
        Lb[i + 8] = lsum1;
    }
#pragma unroll
    for (int n = 0; n < 16; ++n) {
        const int c = n * 8 + 2 * q;
        *(float2*)&Ob[(size_t)i * 128 + c]       = make_float2(o[n][0], o[n][1]);
        *(float2*)&Ob[(size_t)(i + 8) * 128 + c] = make_float2(o[n][2], o[n][3]);
    }
}

// ==== merge kernel: sum 4 j-chunk partials, normalize, transpose, store ====
#define MERGE_SMEM_BYTES (128 * 129 * 4 + 128 * 4)   // 66560

__global__ void __launch_bounds__(256, 1) merge_kernel(float* __restrict__ out)
{
    extern __shared__ __align__(16) float ms[];
    float* Os   = ms;               // [c:128][i:129]
    float* Linv = ms + 128 * 129;

    const int t = threadIdx.x;
    const int iblk = blockIdx.x;
    const int b    = blockIdx.y;

    const float* O0 = g_O + ((size_t)(b * JSPLIT) * 32 + iblk) * (128 * 128);
    const size_t sj = (size_t)32 * 128 * 128;

    if (t < 128) {
        const float* L0 = g_L + ((size_t)(b * JSPLIT) * 32 + iblk) * 128 + t;
        const size_t lj = (size_t)32 * 128;
        float L = L0[0] + L0[lj] + L0[2 * lj] + L0[3 * lj];
        Linv[t] = 1.f / L;
    }

#pragma unroll
    for (int r = 0; r < 16; ++r) {
        int idx = (r * 256 + t) * 4;
        int i = idx >> 7, c = idx & 127;
        float4 a  = *(const float4*)&O0[idx];
        float4 b2 = *(const float4*)&O0[sj + idx];
        float4 c4 = *(const float4*)&O0[2 * sj + idx];
        float4 d4 = *(const float4*)&O0[3 * sj + idx];
        Os[(c + 0) * 129 + i] = a.x + b2.x + c4.x + d4.x;
        Os[(c + 1) * 129 + i] = a.y + b2.y + c4.y + d4.y;
        Os[(c + 2) * 129 + i] = a.z + b2.z + c4.z + d4.z;
        Os[(c + 3) * 129 + i] = a.w + b2.w + c4.w + d4.w;
    }
    __syncthreads();

    const int c = t >> 1, h = t & 1;
    const float* src = Os + c * 129 + 64 * h;
    const float* li  = Linv + 64 * h;
    float* dst = out + ((size_t)b * CH + c) * NPIX + iblk * 128 + 64 * h;
#pragma unroll
    for (int k = 0; k < 16; ++k) {
        ((float4*)dst)[k] = make_float4(src[4 * k]     * li[4 * k],
                                        src[4 * k + 1] * li[4 * k + 1],
                                        src[4 * k + 2] * li[4 * k + 2],
                                        src[4 * k + 3] * li[4 * k + 3]);
    }
}

// ============================================================
extern "C" void kernel_launch(void* const* d_in, const int* in_sizes, int n_in,
                              void* d_out, int out_size)
{
    (void)in_sizes; (void)n_in; (void)out_size;
    const float* x1 = (const float*)d_in[0];
    const float* x2 = (const float*)d_in[1];
    const float* Wq = (const float*)d_in[2];
    const float* bq = (const float*)d_in[3];
    const float* Wk = (const float*)d_in[4];
    const float* bk = (const float*)d_in[5];
    const float* Wv = (const float*)d_in[6];
    const float* bv = (const float*)d_in[7];
    float* out = (float*)d_out;

    cudaFuncSetAttribute(qkv_kernel, cudaFuncAttributeMaxDynamicSharedMemorySize, PROJ_SMEM_BYTES);
    cudaFuncSetAttribute(attn_kernel, cudaFuncAttributeMaxDynamicSharedMemorySize, ATTN_SMEM_BYTES);
    cudaFuncSetAttribute(merge_kernel, cudaFuncAttributeMaxDynamicSharedMemorySize, MERGE_SMEM_BYTES);

    qkv_kernel<<<dim3(NPIX / 128, 3, BATCH), 256, PROJ_SMEM_BYTES>>>(x1, x2, Wq, bq, Wk, bk, Wv, bv);
    attn_kernel<<<dim3(NPIX / BR, JSPLIT, BATCH), 256, ATTN_SMEM_BYTES>>>();
    merge_kernel<<<dim3(NPIX / 128, BATCH), 256, MERGE_SMEM_BYTES>>>(out);
}

// round 13
// speedup vs baseline: 1.0734x; 1.0106x over previous
#include <cuda_runtime.h>
#include <cuda_bf16.h>
#include <stdint.h>
#include <math.h>

#define BATCH 8
#define CH    128
#define NPIX  4096
#define BR    128
#define BC    64
#define NT    (NPIX / BC)   // 64
#define JSPLIT 4
#define TILES_PER_UNIT (NT / JSPLIT)   // 16

// bf16 hi/lo split operands (emulated-fp32 MMA)
__device__ __align__(16) __nv_bfloat16 g_Qhi[BATCH * NPIX * CH];  // [b][n][c]
__device__ __align__(16) __nv_bfloat16 g_Qlo[BATCH * NPIX * CH];
__device__ __align__(16) __nv_bfloat16 g_Khi[BATCH * NPIX * CH];  // [b][n][c]
__device__ __align__(16) __nv_bfloat16 g_Klo[BATCH * NPIX * CH];
__device__ __align__(16) __nv_bfloat16 g_Vhi[BATCH * CH * NPIX];  // [b][c][n]
__device__ __align__(16) __nv_bfloat16 g_Vlo[BATCH * CH * NPIX];

// split-j partial outputs: [b][jc][iblk][i 128][c 128], and row sums
__device__ __align__(16) float g_O[BATCH * JSPLIT * 32 * 128 * 128];  // 64 MB
__device__ __align__(16) float g_L[BATCH * JSPLIT * 32 * 128];

typedef unsigned long long u64;

__device__ __forceinline__ uint32_t smem_u32(const void* p) {
    uint32_t a;
    asm("{ .reg .u64 t; cvta.to.shared.u64 t, %1; cvt.u32.u64 %0, t; }" : "=r"(a) : "l"(p));
    return a;
}
__device__ __forceinline__ void cpasync16(uint32_t dst, const void* src) {
    asm volatile("cp.async.cg.shared.global [%0], [%1], 16;" :: "r"(dst), "l"(src));
}
#define CP_COMMIT() asm volatile("cp.async.commit_group;" ::: "memory")
#define CP_WAIT0()  asm volatile("cp.async.wait_group 0;" ::: "memory")

__device__ __forceinline__ float ex2(float x) {
    float y; asm("ex2.approx.ftz.f32 %0, %1;" : "=f"(y) : "f"(x)); return y;
}

// m16n8k16 row.col bf16 -> fp32, D==C in place
__device__ __forceinline__ void mma16816(float* c,
    uint32_t a0, uint32_t a1, uint32_t a2, uint32_t a3, uint32_t b0, uint32_t b1) {
    asm volatile(
        "mma.sync.aligned.m16n8k16.row.col.f32.bf16.bf16.f32 "
        "{%0,%1,%2,%3}, {%4,%5,%6,%7}, {%8,%9}, {%0,%1,%2,%3};"
        : "+f"(c[0]), "+f"(c[1]), "+f"(c[2]), "+f"(c[3])
        : "r"(a0), "r"(a1), "r"(a2), "r"(a3), "r"(b0), "r"(b1));
}

// ldmatrix x4 non-trans / trans
__device__ __forceinline__ void ldsm4(uint32_t& r0, uint32_t& r1, uint32_t& r2,
                                      uint32_t& r3, uint32_t addr) {
    asm volatile("ldmatrix.sync.aligned.m8n8.x4.shared.b16 {%0,%1,%2,%3}, [%4];"
                 : "=r"(r0), "=r"(r1), "=r"(r2), "=r"(r3) : "r"(addr));
}
__device__ __forceinline__ void ldsm4t(uint32_t& r0, uint32_t& r1, uint32_t& r2,
                                       uint32_t& r3, uint32_t addr) {
    asm volatile("ldmatrix.sync.aligned.m8n8.x4.trans.shared.b16 {%0,%1,%2,%3}, [%4];"
                 : "=r"(r0), "=r"(r1), "=r"(r2), "=r"(r3) : "r"(addr));
}

// pack (pe,po) fp32 pair -> bf16x2 hi + bf16x2 lo (pe in low half)
__device__ __forceinline__ void splitP(float pe, float po, uint32_t& h, uint32_t& l) {
    uint32_t hh;
    asm("cvt.rn.bf16x2.f32 %0, %1, %2;" : "=r"(hh) : "f"(po), "f"(pe));
    __nv_bfloat162 hb = *reinterpret_cast<__nv_bfloat162*>(&hh);
    float2 hf = __bfloat1622float2(hb);
    uint32_t ll;
    asm("cvt.rn.bf16x2.f32 %0, %1, %2;" : "=r"(ll) : "f"(po - hf.y), "f"(pe - hf.x));
    h = hh; l = ll;
}
__device__ __forceinline__ void split2(float a, float b, uint32_t& hi, uint32_t& lo) {
    __nv_bfloat162 h = __floats2bfloat162_rn(a, b);
    float2 hf = __bfloat1622float2(h);
    __nv_bfloat162 l = __floats2bfloat162_rn(a - hf.x, b - hf.y);
    union { __nv_bfloat162 v; uint32_t u; } ch, cl;
    ch.v = h; cl.v = l;
    hi = ch.u; lo = cl.u;
}

#define LOG2E 1.4426950408889634f

// ====== QKV projection on HMMA bf16x3 ======
// grid (32, 2, 8): y==0 -> Q from x1 (swapped orientation, direct [n][c] store)
//                  y==1 -> K (swapped) then V (normal) from x2, X staged once
// smem: Whi[128o][136c] | Wlo | Xhi[128c][136p] | Xlo
#define WHI_B 0
#define WLO_B 34816
#define XHI_B 69632
#define XLO_B 104448
#define PROJ_SMEM_BYTES 139264

__global__ void __launch_bounds__(256, 1) qkv_kernel(
    const float* __restrict__ x1, const float* __restrict__ x2,
    const float* __restrict__ Wq, const float* __restrict__ bq,
    const float* __restrict__ Wk, const float* __restrict__ bk,
    const float* __restrict__ Wv, const float* __restrict__ bv)
{
    extern __shared__ __align__(16) char smc[];
    const uint32_t sb = smem_u32(smc);

    const int t = threadIdx.x;
    const int wid = t >> 5;
    const int lane = t & 31;
    const int l7 = lane & 7;
    const int r8 = lane >> 3;
    const bool isQ = (blockIdx.y == 0);
    const int b = blockIdx.z, p0 = blockIdx.x * 128;

    const float* X = (isQ ? x1 : x2) + (size_t)b * CH * NPIX;

    // ---- stage X tile hi/lo: [c][p+pad] bf16 (once per CTA) ----
#pragma unroll
    for (int r = 0; r < 16; ++r) {
        int idx = t + 256 * r;             // 4096 float4 loads
        int c = idx >> 5, p4 = (idx & 31) * 4;
        float4 x4 = *(const float4*)&X[(size_t)c * NPIX + p0 + p4];
        uint32_t h0, l0, h1, l1;
        split2(x4.x, x4.y, h0, l0);
        split2(x4.z, x4.w, h1, l1);
        *(uint2*)(smc + XHI_B + c * 272 + p4 * 2) = make_uint2(h0, h1);
        *(uint2*)(smc + XLO_B + c * 272 + p4 * 2) = make_uint2(l0, l1);
    }

    const int g = lane >> 2, q4 = lane & 3;
    const int npass = isQ ? 1 : 2;

    for (int pass = 0; pass < npass; ++pass) {
        const float* W    = isQ ? Wq : (pass == 0 ? Wk : Wv);
        const float* bias = isQ ? bq : (pass == 0 ? bk : bv);
        if (pass) __syncthreads();   // prior pass done reading W region

        // ---- stage W hi/lo: [o][c+pad] bf16 ----
#pragma unroll
        for (int r = 0; r < 4; ++r) {
            int task = t + 256 * r;            // 1024 tasks, each 16 c-values
            int o = task >> 3, c16 = (task & 7) * 16;
            const float4* ws = (const float4*)&W[o * CH + c16];
            uint32_t hi[8], lo[8];
#pragma unroll
            for (int j = 0; j < 4; ++j) {
                float4 w4 = ws[j];
                split2(w4.x, w4.y, hi[2 * j], lo[2 * j]);
                split2(w4.z, w4.w, hi[2 * j + 1], lo[2 * j + 1]);
            }
            char* dh = smc + WHI_B + o * 272 + c16 * 2;
            char* dl = smc + WLO_B + o * 272 + c16 * 2;
            ((uint4*)dh)[0] = make_uint4(hi[0], hi[1], hi[2], hi[3]);
            ((uint4*)dh)[1] = make_uint4(hi[4], hi[5], hi[6], hi[7]);
            ((uint4*)dl)[0] = make_uint4(lo[0], lo[1], lo[2], lo[3]);
            ((uint4*)dl)[1] = make_uint4(lo[4], lo[5], lo[6], lo[7]);
        }
        __syncthreads();

        float acc[16][4];
#pragma unroll
        for (int n = 0; n < 16; ++n)
#pragma unroll
            for (int r = 0; r < 4; ++r) acc[n][r] = 0.f;

        if (isQ || pass == 0) {
            // ==== swapped: Out^T[p][o]; A = X (trans ldsm), B = W (non-trans) ====
            // warp covers p rows [wid*16, +16), all 128 o
            const uint32_t aT = sb + XHI_B
                + (uint32_t)((r8 & 1) * 8 + l7) * 272
                + (uint32_t)(wid * 16 + (r8 >> 1) * 8) * 2;
            const uint32_t bW = sb + WHI_B
                + (uint32_t)((r8 >> 1) * 8 + l7) * 272 + (uint32_t)(r8 & 1) * 16;
#pragma unroll
            for (int kk = 0; kk < 8; ++kk) {
                uint32_t a0h, a1h, a2h, a3h, a0l, a1l, a2l, a3l;
                // frag order fix: regs (a0,a2,a1,a3) <- mats 0..3
                ldsm4t(a0h, a2h, a1h, a3h, aT + kk * 16 * 272);
                ldsm4t(a0l, a2l, a1l, a3l, aT + (XLO_B - XHI_B) + kk * 16 * 272);
#pragma unroll
                for (int np = 0; np < 8; ++np) {
                    uint32_t b00, b01, b10, b11, c00, c01, c10, c11;
                    ldsm4(b00, b01, b10, b11, bW + np * 4352 + kk * 32);
                    ldsm4(c00, c01, c10, c11, bW + (WLO_B - WHI_B) + np * 4352 + kk * 32);
                    mma16816(acc[2 * np],     a0h, a1h, a2h, a3h, b00, b01);
                    mma16816(acc[2 * np],     a0l, a1l, a2l, a3l, b00, b01);
                    mma16816(acc[2 * np],     a0h, a1h, a2h, a3h, c00, c01);
                    mma16816(acc[2 * np + 1], a0h, a1h, a2h, a3h, b10, b11);
                    mma16816(acc[2 * np + 1], a0l, a1l, a2l, a3l, b10, b11);
                    mma16816(acc[2 * np + 1], a0h, a1h, a2h, a3h, c10, c11);
                }
            }
            // direct [n][c] epilogue: rows p = wid*16+g (+8), cols o = n*8+2q
            const float qsc = isQ ? LOG2E : 1.0f;
            __nv_bfloat16* dHi = isQ ? g_Qhi : g_Khi;
            __nv_bfloat16* dLo = isQ ? g_Qlo : g_Klo;
            const int p = wid * 16 + g;
            size_t r0 = ((size_t)b * NPIX + p0 + p) * CH;
            size_t r8b = r0 + (size_t)8 * CH;
#pragma unroll
            for (int n = 0; n < 16; ++n) {
                const int o = n * 8 + 2 * q4;
                float2 bo = *(const float2*)&bias[o];
                uint32_t h0, l0, h1, l1;
                split2((acc[n][0] + bo.x) * qsc, (acc[n][1] + bo.y) * qsc, h0, l0);
                split2((acc[n][2] + bo.x) * qsc, (acc[n][3] + bo.y) * qsc, h1, l1);
                *(uint32_t*)(dHi + r0 + o)  = h0;
                *(uint32_t*)(dLo + r0 + o)  = l0;
                *(uint32_t*)(dHi + r8b + o) = h1;
                *(uint32_t*)(dLo + r8b + o) = l1;
            }
        } else {
            // ==== normal: Out[o][p]; A = W (non-trans), B = X (trans) -> V ====
            const uint32_t aH = sb + WHI_B
                + (uint32_t)(wid * 16 + l7 + (r8 & 1) * 8) * 272
                + (uint32_t)((lane >> 4) & 1) * 16;
            const uint32_t aL = aH + (WLO_B - WHI_B);
            const uint32_t bT = sb + XHI_B
                + (uint32_t)((r8 & 1) * 8 + l7) * 272 + (uint32_t)(r8 >> 1) * 16;
#pragma unroll
            for (int kk = 0; kk < 8; ++kk) {
                uint32_t a0h, a1h, a2h, a3h, a0l, a1l, a2l, a3l;
                ldsm4(a0h, a1h, a2h, a3h, aH + kk * 32);
                ldsm4(a0l, a1l, a2l, a3l, aL + kk * 32);
                const uint32_t bk16 = bT + (uint32_t)kk * 16 * 272;
#pragma unroll
                for (int np = 0; np < 8; ++np) {
                    uint32_t b00, b01, b10, b11, c00, c01, c10, c11;
                    ldsm4t(b00, b01, b10, b11, bk16 + np * 32);
                    ldsm4t(c00, c01, c10, c11, bk16 + (XLO_B - XHI_B) + np * 32);
                    mma16816(acc[2 * np],     a0h, a1h, a2h, a3h, b00, b01);
                    mma16816(acc[2 * np],     a0l, a1l, a2l, a3l, b00, b01);
                    mma16816(acc[2 * np],     a0h, a1h, a2h, a3h, c00, c01);
                    mma16816(acc[2 * np + 1], a0h, a1h, a2h, a3h, b10, b11);
                    mma16816(acc[2 * np + 1], a0l, a1l, a2l, a3l, b10, b11);
                    mma16816(acc[2 * np + 1], a0h, a1h, a2h, a3h, c10, c11);
                }
            }
            // V epilogue: [o][p] direct
            const int o0 = wid * 16 + g;
            float bo0 = bv[o0], bo8 = bv[o0 + 8];
            size_t rb0 = ((size_t)b * CH + o0) * NPIX + p0;
            size_t rb8 = rb0 + (size_t)8 * NPIX;
#pragma unroll
            for (int n = 0; n < 16; ++n) {
                const int p = n * 8 + 2 * q4;
                uint32_t h0, l0, h1, l1;
                split2(acc[n][0] + bo0, acc[n][1] + bo0, h0, l0);
                split2(acc[n][2] + bo8, acc[n][3] + bo8, h1, l1);
                *(uint32_t*)(g_Vhi + rb0 + p) = h0;
                *(uint32_t*)(g_Vlo + rb0 + p) = l0;
                *(uint32_t*)(g_Vhi + rb8 + p) = h1;
                *(uint32_t*)(g_Vlo + rb8 + p) = l1;
            }
        }
    }
}

// ==== flash attention partial: HMMA bf16x3, ldmatrix, split-j (16 tiles/unit) ====
#define QHI_B 0
#define QLO_B 34816
#define BUF_B 69632
#define BUFSTRIDE 71680
#define KHI_B(d) (BUF_B + (d) * BUFSTRIDE)
#define VHI_B(d) (KHI_B(d) + 2 * 17408)
#define ATTN_SMEM_BYTES (BUF_B + 2 * BUFSTRIDE)   // 212992

__global__ void __launch_bounds__(256, 1) attn_kernel()
{
    extern __shared__ __align__(16) uint32_t sm32[];
    const uint32_t sb = smem_u32(sm32);

    const int t = threadIdx.x;
    const int wid = t >> 5;
    const int lane = t & 31;
    const int l7 = lane & 7;
    const int r8 = lane >> 3;
    const int iblk = blockIdx.x;
    const int jc   = blockIdx.y;
    const int b    = blockIdx.z;
    const int i0 = iblk * BR;
    const int jt0 = jc * TILES_PER_UNIT;

    // ---- stage Q hi/lo (persistent) + prefetch first tile via cp.async ----
    {
        const char* qh = (const char*)(g_Qhi + ((size_t)b * NPIX + i0) * CH);
        const char* ql = (const char*)(g_Qlo + ((size_t)b * NPIX + i0) * CH);
#pragma unroll
        for (int r = 0; r < 8; ++r) {
            int idx = t + 256 * r;
            int row = idx >> 4, off = idx & 15;
            cpasync16(sb + QHI_B + row * 272 + off * 16, qh + (size_t)idx * 16);
            cpasync16(sb + QLO_B + row * 272 + off * 16, ql + (size_t)idx * 16);
        }
        const int j0 = jt0 * BC;
        const char* kh = (const char*)(g_Khi + ((size_t)b * NPIX + j0) * CH);
        const char* kl = (const char*)(g_Klo + ((size_t)b * NPIX + j0) * CH);
        const char* vh = (const char*)(g_Vhi + (size_t)b * CH * NPIX + j0);
        const char* vl = (const char*)(g_Vlo + (size_t)b * CH * NPIX + j0);
#pragma unroll
        for (int r = 0; r < 4; ++r) {
            int idx = t + 256 * r;
            int row = idx >> 4, off = idx & 15;
            cpasync16(sb + KHI_B(0) + row * 272 + off * 16, kh + (size_t)idx * 16);
            cpasync16(sb + KHI_B(0) + 17408 + row * 272 + off * 16, kl + (size_t)idx * 16);
        }
#pragma unroll
        for (int r = 0; r < 4; ++r) {
            int idx = t + 256 * r;
            int row = idx >> 3, off = idx & 7;
            cpasync16(sb + VHI_B(0) + row * 144 + off * 16,
                      vh + (size_t)row * NPIX * 2 + off * 16);
            cpasync16(sb + VHI_B(0) + 18432 + row * 144 + off * 16,
                      vl + (size_t)row * NPIX * 2 + off * 16);
        }
        CP_COMMIT();
    }

    float o[16][4];
#pragma unroll
    for (int n = 0; n < 16; ++n)
#pragma unroll
        for (int r = 0; r < 4; ++r) o[n][r] = 0.f;
    float lsum0 = 0.f, lsum1 = 0.f;

    const uint32_t aOffH = sb + QHI_B
        + (uint32_t)(wid * 16 + l7 + (r8 & 1) * 8) * 272 + (uint32_t)((lane >> 4) & 1) * 16;
    const uint32_t aOffL = aOffH + (QLO_B - QHI_B);
    const uint32_t bRow = (uint32_t)((r8 >> 1) * 8 + l7);
    const uint32_t bOffK = bRow * 272 + (uint32_t)(r8 & 1) * 16;
    const uint32_t bOffV = bRow * 144 + (uint32_t)(r8 & 1) * 16;

    for (int jt = jt0; jt < jt0 + TILES_PER_UNIT; ++jt) {
        const int d = jt & 1;
        CP_WAIT0();
        __syncthreads();

        if (jt + 1 < jt0 + TILES_PER_UNIT) {
            const int j0n = (jt + 1) * BC, dn = (jt + 1) & 1;
            const char* kh = (const char*)(g_Khi + ((size_t)b * NPIX + j0n) * CH);
            const char* kl = (const char*)(g_Klo + ((size_t)b * NPIX + j0n) * CH);
            const char* vh = (const char*)(g_Vhi + (size_t)b * CH * NPIX + j0n);
            const char* vl = (const char*)(g_Vlo + (size_t)b * CH * NPIX + j0n);
#pragma unroll
            for (int r = 0; r < 4; ++r) {
                int idx = t + 256 * r;
                int row = idx >> 4, off = idx & 15;
                cpasync16(sb + KHI_B(dn) + row * 272 + off * 16, kh + (size_t)idx * 16);
                cpasync16(sb + KHI_B(dn) + 17408 + row * 272 + off * 16, kl + (size_t)idx * 16);
            }
#pragma unroll
            for (int r = 0; r < 4; ++r) {
                int idx = t + 256 * r;
                int row = idx >> 3, off = idx & 7;
                cpasync16(sb + VHI_B(dn) + row * 144 + off * 16,
                          vh + (size_t)row * NPIX * 2 + off * 16);
                cpasync16(sb + VHI_B(dn) + 18432 + row * 144 + off * 16,
                          vl + (size_t)row * NPIX * 2 + off * 16);
            }
            CP_COMMIT();
        }

        float s[8][4];
#pragma unroll
        for (int n = 0; n < 8; ++n)
#pragma unroll
            for (int r = 0; r < 4; ++r) s[n][r] = 0.f;

        const uint32_t kBase = sb + KHI_B(d) + bOffK;
#pragma unroll
        for (int kk = 0; kk < 8; ++kk) {
            uint32_t a0h, a1h, a2h, a3h, a0l, a1l, a2l, a3l;
            ldsm4(a0h, a1h, a2h, a3h, aOffH + kk * 32);
            ldsm4(a0l, a1l, a2l, a3l, aOffL + kk * 32);
#pragma unroll
            for (int np = 0; np < 4; ++np) {
                uint32_t b00, b01, b10, b11, c00, c01, c10, c11;
                ldsm4(b00, b01, b10, b11, kBase + np * 4352 + kk * 32);
                ldsm4(c00, c01, c10, c11, kBase + 17408 + np * 4352 + kk * 32);
                mma16816(s[2 * np],     a0h, a1h, a2h, a3h, b00, b01);
                mma16816(s[2 * np],     a0l, a1l, a2l, a3l, b00, b01);
                mma16816(s[2 * np],     a0h, a1h, a2h, a3h, c00, c01);
                mma16816(s[2 * np + 1], a0h, a1h, a2h, a3h, b10, b11);
                mma16816(s[2 * np + 1], a0l, a1l, a2l, a3l, b10, b11);
                mma16816(s[2 * np + 1], a0h, a1h, a2h, a3h, c10, c11);
            }
        }

#pragma unroll
        for (int n = 0; n < 8; ++n) {
            s[n][0] = ex2(s[n][0]);
            s[n][1] = ex2(s[n][1]);
            s[n][2] = ex2(s[n][2]);
            s[n][3] = ex2(s[n][3]);
            lsum0 += s[n][0] + s[n][1];
            lsum1 += s[n][2] + s[n][3];
        }

        const uint32_t vBase = sb + VHI_B(d) + bOffV;
#pragma unroll
        for (int kk = 0; kk < 4; ++kk) {
            uint32_t pa0h, pa0l, pa1h, pa1l, pa2h, pa2l, pa3h, pa3l;
            splitP(s[2 * kk][0],     s[2 * kk][1],     pa0h, pa0l);
            splitP(s[2 * kk][2],     s[2 * kk][3],     pa1h, pa1l);
            splitP(s[2 * kk + 1][0], s[2 * kk + 1][1], pa2h, pa2l);
            splitP(s[2 * kk + 1][2], s[2 * kk + 1][3], pa3h, pa3l);
#pragma unroll
            for (int n2 = 0; n2 < 8; ++n2) {
                uint32_t b00, b01, b10, b11, c00, c01, c10, c11;
                ldsm4(b00, b01, b10, b11, vBase + n2 * 2304 + kk * 32);
                ldsm4(c00, c01, c10, c11, vBase + 18432 + n2 * 2304 + kk * 32);
                mma16816(o[2 * n2],     pa0h, pa1h, pa2h, pa3h, b00, b01);
                mma16816(o[2 * n2],     pa0l, pa1l, pa2l, pa3l, b00, b01);
                mma16816(o[2 * n2],     pa0h, pa1h, pa2h, pa3h, c00, c01);
                mma16816(o[2 * n2 + 1], pa0h, pa1h, pa2h, pa3h, b10, b11);
                mma16816(o[2 * n2 + 1], pa0l, pa1l, pa2l, pa3l, b10, b11);
                mma16816(o[2 * n2 + 1], pa0h, pa1h, pa2h, pa3h, c10, c11);
            }
        }
        __syncthreads();
    }

    lsum0 += __shfl_xor_sync(0xffffffffu, lsum0, 1);
    lsum0 += __shfl_xor_sync(0xffffffffu, lsum0, 2);
    lsum1 += __shfl_xor_sync(0xffffffffu, lsum1, 1);
    lsum1 += __shfl_xor_sync(0xffffffffu, lsum1, 2);

    const size_t unit = ((size_t)(b * JSPLIT + jc) * 32 + iblk);
    float* Ob = g_O + unit * (128 * 128);
    float* Lb = g_L + unit * 128;
    const int g = lane >> 2, q = lane & 3;
    const int i = wid * 16 + g;
    if ((lane & 3) == 0) {
        Lb[i]     = lsum0;
        Lb[i + 8] = lsum1;
    }
#pragma unroll
    for (int n = 0; n < 16; ++n) {
        const int c = n * 8 + 2 * q;
        *(float2*)&Ob[(size_t)i * 128 + c]       = make_float2(o[n][0], o[n][1]);
        *(float2*)&Ob[(size_t)(i + 8) * 128 + c] = make_float2(o[n][2], o[n][3]);
    }
}

// ==== merge kernel: sum 4 j-chunk partials, normalize, transpose, store ====
#define MERGE_SMEM_BYTES (128 * 129 * 4 + 128 * 4)   // 66560

__global__ void __launch_bounds__(256, 1) merge_kernel(float* __restrict__ out)
{
    extern __shared__ __align__(16) float ms[];
    float* Os   = ms;               // [c:128][i:129]
    float* Linv = ms + 128 * 129;

    const int t = threadIdx.x;
    const int iblk = blockIdx.x;
    const int b    = blockIdx.y;

    const float* O0 = g_O + ((size_t)(b * JSPLIT) * 32 + iblk) * (128 * 128);
    const size_t sj = (size_t)32 * 128 * 128;

    if (t < 128) {
        const float* L0 = g_L + ((size_t)(b * JSPLIT) * 32 + iblk) * 128 + t;
        const size_t lj = (size_t)32 * 128;
        float L = L0[0] + L0[lj] + L0[2 * lj] + L0[3 * lj];
        Linv[t] = 1.f / L;
    }

#pragma unroll
    for (int r = 0; r < 16; ++r) {
        int idx = (r * 256 + t) * 4;
        int i = idx >> 7, c = idx & 127;
        float4 a  = *(const float4*)&O0[idx];
        float4 b2 = *(const float4*)&O0[sj + idx];
        float4 c4 = *(const float4*)&O0[2 * sj + idx];
        float4 d4 = *(const float4*)&O0[3 * sj + idx];
        Os[(c + 0) * 129 + i] = a.x + b2.x + c4.x + d4.x;
        Os[(c + 1) * 129 + i] = a.y + b2.y + c4.y + d4.y;
        Os[(c + 2) * 129 + i] = a.z + b2.z + c4.z + d4.z;
        Os[(c + 3) * 129 + i] = a.w + b2.w + c4.w + d4.w;
    }
    __syncthreads();

    const int c = t >> 1, h = t & 1;
    const float* src = Os + c * 129 + 64 * h;
    const float* li  = Linv + 64 * h;
    float* dst = out + ((size_t)b * CH + c) * NPIX + iblk * 128 + 64 * h;
#pragma unroll
    for (int k = 0; k < 16; ++k) {
        ((float4*)dst)[k] = make_float4(src[4 * k]     * li[4 * k],
                                        src[4 * k + 1] * li[4 * k + 1],
                                        src[4 * k + 2] * li[4 * k + 2],
                                        src[4 * k + 3] * li[4 * k + 3]);
    }
}

// ============================================================
extern "C" void kernel_launch(void* const* d_in, const int* in_sizes, int n_in,
                              void* d_out, int out_size)
{
    (void)in_sizes; (void)n_in; (void)out_size;
    const float* x1 = (const float*)d_in[0];
    const float* x2 = (const float*)d_in[1];
    const float* Wq = (const float*)d_in[2];
    const float* bq = (const float*)d_in[3];
    const float* Wk = (const float*)d_in[4];
    const float* bk = (const float*)d_in[5];
    const float* Wv = (const float*)d_in[6];
    const float* bv = (const float*)d_in[7];
    float* out = (float*)d_out;

    cudaFuncSetAttribute(qkv_kernel, cudaFuncAttributeMaxDynamicSharedMemorySize, PROJ_SMEM_BYTES);
    cudaFuncSetAttribute(attn_kernel, cudaFuncAttributeMaxDynamicSharedMemorySize, ATTN_SMEM_BYTES);
    cudaFuncSetAttribute(merge_kernel, cudaFuncAttributeMaxDynamicSharedMemorySize, MERGE_SMEM_BYTES);

    qkv_kernel<<<dim3(NPIX / 128, 2, BATCH), 256, PROJ_SMEM_BYTES>>>(x1, x2, Wq, bq, Wk, bk, Wv, bv);
    attn_kernel<<<dim3(NPIX / BR, JSPLIT, BATCH), 256, ATTN_SMEM_BYTES>>>();
    merge_kernel<<<dim3(NPIX / 128, BATCH), 256, MERGE_SMEM_BYTES>>>(out);
}

// round 14
// speedup vs baseline: 1.0749x; 1.0014x over previous
#include <cuda_runtime.h>
#include <cuda_bf16.h>
#include <stdint.h>
#include <math.h>

#define BATCH 8
#define CH    128
#define NPIX  4096
#define BR    128
#define BC    64
#define NT    (NPIX / BC)   // 64
#define JSPLIT 4
#define TILES_PER_UNIT (NT / JSPLIT)   // 16

// bf16 hi/lo split operands (emulated-fp32 MMA)
__device__ __align__(16) __nv_bfloat16 g_Qhi[BATCH * NPIX * CH];  // [b][n][c]
__device__ __align__(16) __nv_bfloat16 g_Qlo[BATCH * NPIX * CH];
__device__ __align__(16) __nv_bfloat16 g_Khi[BATCH * NPIX * CH];  // [b][n][c]
__device__ __align__(16) __nv_bfloat16 g_Klo[BATCH * NPIX * CH];
__device__ __align__(16) __nv_bfloat16 g_Vhi[BATCH * CH * NPIX];  // [b][c][n]
__device__ __align__(16) __nv_bfloat16 g_Vlo[BATCH * CH * NPIX];

// split-j partial outputs: [b][jc][iblk][i 128][c 128], and row sums
__device__ __align__(16) float g_O[BATCH * JSPLIT * 32 * 128 * 128];  // 64 MB
__device__ __align__(16) float g_L[BATCH * JSPLIT * 32 * 128];

typedef unsigned long long u64;

__device__ __forceinline__ uint32_t smem_u32(const void* p) {
    uint32_t a;
    asm("{ .reg .u64 t; cvta.to.shared.u64 t, %1; cvt.u32.u64 %0, t; }" : "=r"(a) : "l"(p));
    return a;
}
__device__ __forceinline__ void cpasync16(uint32_t dst, const void* src) {
    asm volatile("cp.async.cg.shared.global [%0], [%1], 16;" :: "r"(dst), "l"(src));
}
#define CP_COMMIT() asm volatile("cp.async.commit_group;" ::: "memory")
#define CP_WAIT0()  asm volatile("cp.async.wait_group 0;" ::: "memory")

__device__ __forceinline__ float ex2(float x) {
    float y; asm("ex2.approx.ftz.f32 %0, %1;" : "=f"(y) : "f"(x)); return y;
}

// m16n8k16 row.col bf16 -> fp32, D==C in place
__device__ __forceinline__ void mma16816(float* c,
    uint32_t a0, uint32_t a1, uint32_t a2, uint32_t a3, uint32_t b0, uint32_t b1) {
    asm volatile(
        "mma.sync.aligned.m16n8k16.row.col.f32.bf16.bf16.f32 "
        "{%0,%1,%2,%3}, {%4,%5,%6,%7}, {%8,%9}, {%0,%1,%2,%3};"
        : "+f"(c[0]), "+f"(c[1]), "+f"(c[2]), "+f"(c[3])
        : "r"(a0), "r"(a1), "r"(a2), "r"(a3), "r"(b0), "r"(b1));
}

// ldmatrix x4 non-trans / trans
__device__ __forceinline__ void ldsm4(uint32_t& r0, uint32_t& r1, uint32_t& r2,
                                      uint32_t& r3, uint32_t addr) {
    asm volatile("ldmatrix.sync.aligned.m8n8.x4.shared.b16 {%0,%1,%2,%3}, [%4];"
                 : "=r"(r0), "=r"(r1), "=r"(r2), "=r"(r3) : "r"(addr));
}
__device__ __forceinline__ void ldsm4t(uint32_t& r0, uint32_t& r1, uint32_t& r2,
                                       uint32_t& r3, uint32_t addr) {
    asm volatile("ldmatrix.sync.aligned.m8n8.x4.trans.shared.b16 {%0,%1,%2,%3}, [%4];"
                 : "=r"(r0), "=r"(r1), "=r"(r2), "=r"(r3) : "r"(addr));
}

// pack (pe,po) fp32 pair -> bf16x2 hi + bf16x2 lo (pe in low half)
__device__ __forceinline__ void splitP(float pe, float po, uint32_t& h, uint32_t& l) {
    uint32_t hh;
    asm("cvt.rn.bf16x2.f32 %0, %1, %2;" : "=r"(hh) : "f"(po), "f"(pe));
    __nv_bfloat162 hb = *reinterpret_cast<__nv_bfloat162*>(&hh);
    float2 hf = __bfloat1622float2(hb);
    uint32_t ll;
    asm("cvt.rn.bf16x2.f32 %0, %1, %2;" : "=r"(ll) : "f"(po - hf.y), "f"(pe - hf.x));
    h = hh; l = ll;
}
__device__ __forceinline__ void split2(float a, float b, uint32_t& hi, uint32_t& lo) {
    __nv_bfloat162 h = __floats2bfloat162_rn(a, b);
    float2 hf = __bfloat1622float2(h);
    __nv_bfloat162 l = __floats2bfloat162_rn(a - hf.x, b - hf.y);
    union { __nv_bfloat162 v; uint32_t u; } ch, cl;
    ch.v = h; cl.v = l;
    hi = ch.u; lo = cl.u;
}

#define LOG2E 1.4426950408889634f

// ====== QKV projection on HMMA bf16x3 (unchanged from r13) ======
#define WHI_B 0
#define WLO_B 34816
#define XHI_B 69632
#define XLO_B 104448
#define PROJ_SMEM_BYTES 139264

__global__ void __launch_bounds__(256, 1) qkv_kernel(
    const float* __restrict__ x1, const float* __restrict__ x2,
    const float* __restrict__ Wq, const float* __restrict__ bq,
    const float* __restrict__ Wk, const float* __restrict__ bk,
    const float* __restrict__ Wv, const float* __restrict__ bv)
{
    extern __shared__ __align__(16) char smc[];
    const uint32_t sb = smem_u32(smc);

    const int t = threadIdx.x;
    const int wid = t >> 5;
    const int lane = t & 31;
    const int l7 = lane & 7;
    const int r8 = lane >> 3;
    const bool isQ = (blockIdx.y == 0);
    const int b = blockIdx.z, p0 = blockIdx.x * 128;

    const float* X = (isQ ? x1 : x2) + (size_t)b * CH * NPIX;

#pragma unroll
    for (int r = 0; r < 16; ++r) {
        int idx = t + 256 * r;
        int c = idx >> 5, p4 = (idx & 31) * 4;
        float4 x4 = *(const float4*)&X[(size_t)c * NPIX + p0 + p4];
        uint32_t h0, l0, h1, l1;
        split2(x4.x, x4.y, h0, l0);
        split2(x4.z, x4.w, h1, l1);
        *(uint2*)(smc + XHI_B + c * 272 + p4 * 2) = make_uint2(h0, h1);
        *(uint2*)(smc + XLO_B + c * 272 + p4 * 2) = make_uint2(l0, l1);
    }

    const int g = lane >> 2, q4 = lane & 3;
    const int npass = isQ ? 1 : 2;

    for (int pass = 0; pass < npass; ++pass) {
        const float* W    = isQ ? Wq : (pass == 0 ? Wk : Wv);
        const float* bias = isQ ? bq : (pass == 0 ? bk : bv);
        if (pass) __syncthreads();

#pragma unroll
        for (int r = 0; r < 4; ++r) {
            int task = t + 256 * r;
            int o = task >> 3, c16 = (task & 7) * 16;
            const float4* ws = (const float4*)&W[o * CH + c16];
            uint32_t hi[8], lo[8];
#pragma unroll
            for (int j = 0; j < 4; ++j) {
                float4 w4 = ws[j];
                split2(w4.x, w4.y, hi[2 * j], lo[2 * j]);
                split2(w4.z, w4.w, hi[2 * j + 1], lo[2 * j + 1]);
            }
            char* dh = smc + WHI_B + o * 272 + c16 * 2;
            char* dl = smc + WLO_B + o * 272 + c16 * 2;
            ((uint4*)dh)[0] = make_uint4(hi[0], hi[1], hi[2], hi[3]);
            ((uint4*)dh)[1] = make_uint4(hi[4], hi[5], hi[6], hi[7]);
            ((uint4*)dl)[0] = make_uint4(lo[0], lo[1], lo[2], lo[3]);
            ((uint4*)dl)[1] = make_uint4(lo[4], lo[5], lo[6], lo[7]);
        }
        __syncthreads();

        float acc[16][4];
#pragma unroll
        for (int n = 0; n < 16; ++n)
#pragma unroll
            for (int r = 0; r < 4; ++r) acc[n][r] = 0.f;

        if (isQ || pass == 0) {
            const uint32_t aT = sb + XHI_B
                + (uint32_t)((r8 & 1) * 8 + l7) * 272
                + (uint32_t)(wid * 16 + (r8 >> 1) * 8) * 2;
            const uint32_t bW = sb + WHI_B
                + (uint32_t)((r8 >> 1) * 8 + l7) * 272 + (uint32_t)(r8 & 1) * 16;
#pragma unroll
            for (int kk = 0; kk < 8; ++kk) {
                uint32_t a0h, a1h, a2h, a3h, a0l, a1l, a2l, a3l;
                ldsm4t(a0h, a2h, a1h, a3h, aT + kk * 16 * 272);
                ldsm4t(a0l, a2l, a1l, a3l, aT + (XLO_B - XHI_B) + kk * 16 * 272);
#pragma unroll
                for (int np = 0; np < 8; ++np) {
                    uint32_t b00, b01, b10, b11, c00, c01, c10, c11;
                    ldsm4(b00, b01, b10, b11, bW + np * 4352 + kk * 32);
                    ldsm4(c00, c01, c10, c11, bW + (WLO_B - WHI_B) + np * 4352 + kk * 32);
                    mma16816(acc[2 * np],     a0h, a1h, a2h, a3h, b00, b01);
                    mma16816(acc[2 * np],     a0l, a1l, a2l, a3l, b00, b01);
                    mma16816(acc[2 * np],     a0h, a1h, a2h, a3h, c00, c01);
                    mma16816(acc[2 * np + 1], a0h, a1h, a2h, a3h, b10, b11);
                    mma16816(acc[2 * np + 1], a0l, a1l, a2l, a3l, b10, b11);
                    mma16816(acc[2 * np + 1], a0h, a1h, a2h, a3h, c10, c11);
                }
            }
            const float qsc = isQ ? LOG2E : 1.0f;
            __nv_bfloat16* dHi = isQ ? g_Qhi : g_Khi;
            __nv_bfloat16* dLo = isQ ? g_Qlo : g_Klo;
            const int p = wid * 16 + g;
            size_t r0 = ((size_t)b * NPIX + p0 + p) * CH;
            size_t r8b = r0 + (size_t)8 * CH;
#pragma unroll
            for (int n = 0; n < 16; ++n) {
                const int o = n * 8 + 2 * q4;
                float2 bo = *(const float2*)&bias[o];
                uint32_t h0, l0, h1, l1;
                split2((acc[n][0] + bo.x) * qsc, (acc[n][1] + bo.y) * qsc, h0, l0);
                split2((acc[n][2] + bo.x) * qsc, (acc[n][3] + bo.y) * qsc, h1, l1);
                *(uint32_t*)(dHi + r0 + o)  = h0;
                *(uint32_t*)(dLo + r0 + o)  = l0;
                *(uint32_t*)(dHi + r8b + o) = h1;
                *(uint32_t*)(dLo + r8b + o) = l1;
            }
        } else {
            const uint32_t aH = sb + WHI_B
                + (uint32_t)(wid * 16 + l7 + (r8 & 1) * 8) * 272
                + (uint32_t)((lane >> 4) & 1) * 16;
            const uint32_t aL = aH + (WLO_B - WHI_B);
            const uint32_t bT = sb + XHI_B
                + (uint32_t)((r8 & 1) * 8 + l7) * 272 + (uint32_t)(r8 >> 1) * 16;
#pragma unroll
            for (int kk = 0; kk < 8; ++kk) {
                uint32_t a0h, a1h, a2h, a3h, a0l, a1l, a2l, a3l;
                ldsm4(a0h, a1h, a2h, a3h, aH + kk * 32);
                ldsm4(a0l, a1l, a2l, a3l, aL + kk * 32);
                const uint32_t bk16 = bT + (uint32_t)kk * 16 * 272;
#pragma unroll
                for (int np = 0; np < 8; ++np) {
                    uint32_t b00, b01, b10, b11, c00, c01, c10, c11;
                    ldsm4t(b00, b01, b10, b11, bk16 + np * 32);
                    ldsm4t(c00, c01, c10, c11, bk16 + (XLO_B - XHI_B) + np * 32);
                    mma16816(acc[2 * np],     a0h, a1h, a2h, a3h, b00, b01);
                    mma16816(acc[2 * np],     a0l, a1l, a2l, a3l, b00, b01);
                    mma16816(acc[2 * np],     a0h, a1h, a2h, a3h, c00, c01);
                    mma16816(acc[2 * np + 1], a0h, a1h, a2h, a3h, b10, b11);
                    mma16816(acc[2 * np + 1], a0l, a1l, a2l, a3l, b10, b11);
                    mma16816(acc[2 * np + 1], a0h, a1h, a2h, a3h, c10, c11);
                }
            }
            const int o0 = wid * 16 + g;
            float bo0 = bv[o0], bo8 = bv[o0 + 8];
            size_t rb0 = ((size_t)b * CH + o0) * NPIX + p0;
            size_t rb8 = rb0 + (size_t)8 * NPIX;
#pragma unroll
            for (int n = 0; n < 16; ++n) {
                const int p = n * 8 + 2 * q4;
                uint32_t h0, l0, h1, l1;
                split2(acc[n][0] + bo0, acc[n][1] + bo0, h0, l0);
                split2(acc[n][2] + bo8, acc[n][3] + bo8, h1, l1);
                *(uint32_t*)(g_Vhi + rb0 + p) = h0;
                *(uint32_t*)(g_Vlo + rb0 + p) = l0;
                *(uint32_t*)(g_Vhi + rb8 + p) = h1;
                *(uint32_t*)(g_Vlo + rb8 + p) = l1;
            }
        }
    }
}

// ==== flash attention partial: term-major MMA ordering (RAW-chain break) ====
#define QHI_B 0
#define QLO_B 34816
#define BUF_B 69632
#define BUFSTRIDE 71680
#define KHI_B(d) (BUF_B + (d) * BUFSTRIDE)
#define VHI_B(d) (KHI_B(d) + 2 * 17408)
#define ATTN_SMEM_BYTES (BUF_B + 2 * BUFSTRIDE)   // 212992

__global__ void __launch_bounds__(256, 1) attn_kernel()
{
    extern __shared__ __align__(16) uint32_t sm32[];
    const uint32_t sb = smem_u32(sm32);

    const int t = threadIdx.x;
    const int wid = t >> 5;
    const int lane = t & 31;
    const int l7 = lane & 7;
    const int r8 = lane >> 3;
    const int iblk = blockIdx.x;
    const int jc   = blockIdx.y;
    const int b    = blockIdx.z;
    const int i0 = iblk * BR;
    const int jt0 = jc * TILES_PER_UNIT;

    {
        const char* qh = (const char*)(g_Qhi + ((size_t)b * NPIX + i0) * CH);
        const char* ql = (const char*)(g_Qlo + ((size_t)b * NPIX + i0) * CH);
#pragma unroll
        for (int r = 0; r < 8; ++r) {
            int idx = t + 256 * r;
            int row = idx >> 4, off = idx & 15;
            cpasync16(sb + QHI_B + row * 272 + off * 16, qh + (size_t)idx * 16);
            cpasync16(sb + QLO_B + row * 272 + off * 16, ql + (size_t)idx * 16);
        }
        const int j0 = jt0 * BC;
        const char* kh = (const char*)(g_Khi + ((size_t)b * NPIX + j0) * CH);
        const char* kl = (const char*)(g_Klo + ((size_t)b * NPIX + j0) * CH);
        const char* vh = (const char*)(g_Vhi + (size_t)b * CH * NPIX + j0);
        const char* vl = (const char*)(g_Vlo + (size_t)b * CH * NPIX + j0);
#pragma unroll
        for (int r = 0; r < 4; ++r) {
            int idx = t + 256 * r;
            int row = idx >> 4, off = idx & 15;
            cpasync16(sb + KHI_B(0) + row * 272 + off * 16, kh + (size_t)idx * 16);
            cpasync16(sb + KHI_B(0) + 17408 + row * 272 + off * 16, kl + (size_t)idx * 16);
        }
#pragma unroll
        for (int r = 0; r < 4; ++r) {
            int idx = t + 256 * r;
            int row = idx >> 3, off = idx & 7;
            cpasync16(sb + VHI_B(0) + row * 144 + off * 16,
                      vh + (size_t)row * NPIX * 2 + off * 16);
            cpasync16(sb + VHI_B(0) + 18432 + row * 144 + off * 16,
                      vl + (size_t)row * NPIX * 2 + off * 16);
        }
        CP_COMMIT();
    }

    float o[16][4];
#pragma unroll
    for (int n = 0; n < 16; ++n)
#pragma unroll
        for (int r = 0; r < 4; ++r) o[n][r] = 0.f;
    float lsum0 = 0.f, lsum1 = 0.f;

    const uint32_t aOffH = sb + QHI_B
        + (uint32_t)(wid * 16 + l7 + (r8 & 1) * 8) * 272 + (uint32_t)((lane >> 4) & 1) * 16;
    const uint32_t aOffL = aOffH + (QLO_B - QHI_B);
    const uint32_t bRow = (uint32_t)((r8 >> 1) * 8 + l7);
    const uint32_t bOffK = bRow * 272 + (uint32_t)(r8 & 1) * 16;
    const uint32_t bOffV = bRow * 144 + (uint32_t)(r8 & 1) * 16;

    for (int jt = jt0; jt < jt0 + TILES_PER_UNIT; ++jt) {
        const int d = jt & 1;
        CP_WAIT0();
        __syncthreads();

        if (jt + 1 < jt0 + TILES_PER_UNIT) {
            const int j0n = (jt + 1) * BC, dn = (jt + 1) & 1;
            const char* kh = (const char*)(g_Khi + ((size_t)b * NPIX + j0n) * CH);
            const char* kl = (const char*)(g_Klo + ((size_t)b * NPIX + j0n) * CH);
            const char* vh = (const char*)(g_Vhi + (size_t)b * CH * NPIX + j0n);
            const char* vl = (const char*)(g_Vlo + (size_t)b * CH * NPIX + j0n);
#pragma unroll
            for (int r = 0; r < 4; ++r) {
                int idx = t + 256 * r;
                int row = idx >> 4, off = idx & 15;
                cpasync16(sb + KHI_B(dn) + row * 272 + off * 16, kh + (size_t)idx * 16);
                cpasync16(sb + KHI_B(dn) + 17408 + row * 272 + off * 16, kl + (size_t)idx * 16);
            }
#pragma unroll
            for (int r = 0; r < 4; ++r) {
                int idx = t + 256 * r;
                int row = idx >> 3, off = idx & 7;
                cpasync16(sb + VHI_B(dn) + row * 144 + off * 16,
                          vh + (size_t)row * NPIX * 2 + off * 16);
                cpasync16(sb + VHI_B(dn) + 18432 + row * 144 + off * 16,
                          vl + (size_t)row * NPIX * 2 + off * 16);
            }
            CP_COMMIT();
        }

        // ---- S = Q K^T, term-major: hh(all acc) -> lh(all) -> hl(all) ----
        float s[8][4];
#pragma unroll
        for (int n = 0; n < 8; ++n)
#pragma unroll
            for (int r = 0; r < 4; ++r) s[n][r] = 0.f;

        const uint32_t kBase = sb + KHI_B(d) + bOffK;
#pragma unroll
        for (int kk = 0; kk < 8; ++kk) {
            uint32_t a0h, a1h, a2h, a3h, a0l, a1l, a2l, a3l;
            ldsm4(a0h, a1h, a2h, a3h, aOffH + kk * 32);
            ldsm4(a0l, a1l, a2l, a3l, aOffL + kk * 32);
            uint32_t bk[4][4], ck[4][4];
#pragma unroll
            for (int np = 0; np < 4; ++np) {
                ldsm4(bk[np][0], bk[np][1], bk[np][2], bk[np][3],
                      kBase + np * 4352 + kk * 32);
                ldsm4(ck[np][0], ck[np][1], ck[np][2], ck[np][3],
                      kBase + 17408 + np * 4352 + kk * 32);
            }
#pragma unroll
            for (int np = 0; np < 4; ++np) {    // term 1: Qhi*Khi
                mma16816(s[2 * np],     a0h, a1h, a2h, a3h, bk[np][0], bk[np][1]);
                mma16816(s[2 * np + 1], a0h, a1h, a2h, a3h, bk[np][2], bk[np][3]);
            }
#pragma unroll
            for (int np = 0; np < 4; ++np) {    // term 2: Qlo*Khi
                mma16816(s[2 * np],     a0l, a1l, a2l, a3l, bk[np][0], bk[np][1]);
                mma16816(s[2 * np + 1], a0l, a1l, a2l, a3l, bk[np][2], bk[np][3]);
            }
#pragma unroll
            for (int np = 0; np < 4; ++np) {    // term 3: Qhi*Klo
                mma16816(s[2 * np],     a0h, a1h, a2h, a3h, ck[np][0], ck[np][1]);
                mma16816(s[2 * np + 1], a0h, a1h, a2h, a3h, ck[np][2], ck[np][3]);
            }
        }

#pragma unroll
        for (int n = 0; n < 8; ++n) {
            s[n][0] = ex2(s[n][0]);
            s[n][1] = ex2(s[n][1]);
            s[n][2] = ex2(s[n][2]);
            s[n][3] = ex2(s[n][3]);
            lsum0 += s[n][0] + s[n][1];
            lsum1 += s[n][2] + s[n][3];
        }

        // ---- O += P V, term-major within n2-halves ----
        const uint32_t vBase = sb + VHI_B(d) + bOffV;
#pragma unroll
        for (int kk = 0; kk < 4; ++kk) {
            uint32_t pa0h, pa0l, pa1h, pa1l, pa2h, pa2l, pa3h, pa3l;
            splitP(s[2 * kk][0],     s[2 * kk][1],     pa0h, pa0l);
            splitP(s[2 * kk][2],     s[2 * kk][3],     pa1h, pa1l);
            splitP(s[2 * kk + 1][0], s[2 * kk + 1][1], pa2h, pa2l);
            splitP(s[2 * kk + 1][2], s[2 * kk + 1][3], pa3h, pa3l);
#pragma unroll
            for (int hf = 0; hf < 2; ++hf) {
                uint32_t vb[4][4], vc[4][4];
#pragma unroll
                for (int m = 0; m < 4; ++m) {
                    const int n2 = hf * 4 + m;
                    ldsm4(vb[m][0], vb[m][1], vb[m][2], vb[m][3],
                          vBase + n2 * 2304 + kk * 32);
                    ldsm4(vc[m][0], vc[m][1], vc[m][2], vc[m][3],
                          vBase + 18432 + n2 * 2304 + kk * 32);
                }
#pragma unroll
                for (int m = 0; m < 4; ++m) {   // term 1: Phi*Vhi
                    const int n2 = hf * 4 + m;
                    mma16816(o[2 * n2],     pa0h, pa1h, pa2h, pa3h, vb[m][0], vb[m][1]);
                    mma16816(o[2 * n2 + 1], pa0h, pa1h, pa2h, pa3h, vb[m][2], vb[m][3]);
                }
#pragma unroll
                for (int m = 0; m < 4; ++m) {   // term 2: Plo*Vhi
                    const int n2 = hf * 4 + m;
                    mma16816(o[2 * n2],     pa0l, pa1l, pa2l, pa3l, vb[m][0], vb[m][1]);
                    mma16816(o[2 * n2 + 1], pa0l, pa1l, pa2l, pa3l, vb[m][2], vb[m][3]);
                }
#pragma unroll
                for (int m = 0; m < 4; ++m) {   // term 3: Phi*Vlo
                    const int n2 = hf * 4 + m;
                    mma16816(o[2 * n2],     pa0h, pa1h, pa2h, pa3h, vc[m][0], vc[m][1]);
                    mma16816(o[2 * n2 + 1], pa0h, pa1h, pa2h, pa3h, vc[m][2], vc[m][3]);
                }
            }
        }
        __syncthreads();
    }

    lsum0 += __shfl_xor_sync(0xffffffffu, lsum0, 1);
    lsum0 += __shfl_xor_sync(0xffffffffu, lsum0, 2);
    lsum1 += __shfl_xor_sync(0xffffffffu, lsum1, 1);
    lsum1 += __shfl_xor_sync(0xffffffffu, lsum1, 2);

    const size_t unit = ((size_t)(b * JSPLIT + jc) * 32 + iblk);
    float* Ob = g_O + unit * (128 * 128);
    float* Lb = g_L + unit * 128;
    const int g = lane >> 2, q = lane & 3;
    const int i = wid * 16 + g;
    if ((lane & 3) == 0) {
        Lb[i]     = lsum0;
        Lb[i + 8] = lsum1;
    }
#pragma unroll
    for (int n = 0; n < 16; ++n) {
        const int c = n * 8 + 2 * q;
        *(float2*)&Ob[(size_t)i * 128 + c]       = make_float2(o[n][0], o[n][1]);
        *(float2*)&Ob[(size_t)(i + 8) * 128 + c] = make_float2(o[n][2], o[n][3]);
    }
}

// ==== merge kernel: sum 4 j-chunk partials, normalize, transpose, store ====
#define MERGE_SMEM_BYTES (128 * 129 * 4 + 128 * 4)   // 66560

__global__ void __launch_bounds__(256, 1) merge_kernel(float* __restrict__ out)
{
    extern __shared__ __align__(16) float ms[];
    float* Os   = ms;               // [c:128][i:129]
    float* Linv = ms + 128 * 129;

    const int t = threadIdx.x;
    const int iblk = blockIdx.x;
    const int b    = blockIdx.y;

    const float* O0 = g_O + ((size_t)(b * JSPLIT) * 32 + iblk) * (128 * 128);
    const size_t sj = (size_t)32 * 128 * 128;

    if (t < 128) {
        const float* L0 = g_L + ((size_t)(b * JSPLIT) * 32 + iblk) * 128 + t;
        const size_t lj = (size_t)32 * 128;
        float L = L0[0] + L0[lj] + L0[2 * lj] + L0[3 * lj];
        Linv[t] = 1.f / L;
    }

#pragma unroll
    for (int r = 0; r < 16; ++r) {
        int idx = (r * 256 + t) * 4;
        int i = idx >> 7, c = idx & 127;
        float4 a  = *(const float4*)&O0[idx];
        float4 b2 = *(const float4*)&O0[sj + idx];
        float4 c4 = *(const float4*)&O0[2 * sj + idx];
        float4 d4 = *(const float4*)&O0[3 * sj + idx];
        Os[(c + 0) * 129 + i] = a.x + b2.x + c4.x + d4.x;
        Os[(c + 1) * 129 + i] = a.y + b2.y + c4.y + d4.y;
        Os[(c + 2) * 129 + i] = a.z + b2.z + c4.z + d4.z;
        Os[(c + 3) * 129 + i] = a.w + b2.w + c4.w + d4.w;
    }
    __syncthreads();

    const int c = t >> 1, h = t & 1;
    const float* src = Os + c * 129 + 64 * h;
    const float* li  = Linv + 64 * h;
    float* dst = out + ((size_t)b * CH + c) * NPIX + iblk * 128 + 64 * h;
#pragma unroll
    for (int k = 0; k < 16; ++k) {
        ((float4*)dst)[k] = make_float4(src[4 * k]     * li[4 * k],
                                        src[4 * k + 1] * li[4 * k + 1],
                                        src[4 * k + 2] * li[4 * k + 2],
                                        src[4 * k + 3] * li[4 * k + 3]);
    }
}

// ============================================================
extern "C" void kernel_launch(void* const* d_in, const int* in_sizes, int n_in,
                              void* d_out, int out_size)
{
    (void)in_sizes; (void)n_in; (void)out_size;
    const float* x1 = (const float*)d_in[0];
    const float* x2 = (const float*)d_in[1];
    const float* Wq = (const float*)d_in[2];
    const float* bq = (const float*)d_in[3];
    const float* Wk = (const float*)d_in[4];
    const float* bk = (const float*)d_in[5];
    const float* Wv = (const float*)d_in[6];
    const float* bv = (const float*)d_in[7];
    float* out = (float*)d_out;

    cudaFuncSetAttribute(qkv_kernel, cudaFuncAttributeMaxDynamicSharedMemorySize, PROJ_SMEM_BYTES);
    cudaFuncSetAttribute(attn_kernel, cudaFuncAttributeMaxDynamicSharedMemorySize, ATTN_SMEM_BYTES);
    cudaFuncSetAttribute(merge_kernel, cudaFuncAttributeMaxDynamicSharedMemorySize, MERGE_SMEM_BYTES);

    qkv_kernel<<<dim3(NPIX / 128, 2, BATCH), 256, PROJ_SMEM_BYTES>>>(x1, x2, Wq, bq, Wk, bk, Wv, bv);
    attn_kernel<<<dim3(NPIX / BR, JSPLIT, BATCH), 256, ATTN_SMEM_BYTES>>>();
    merge_kernel<<<dim3(NPIX / 128, BATCH), 256, MERGE_SMEM_BYTES>>>(out);
}

// round 15
// speedup vs baseline: 1.4214x; 1.3224x over previous
#include <cuda_runtime.h>
#include <cuda_bf16.h>
#include <cuda_fp16.h>
#include <stdint.h>
#include <math.h>

#define BATCH 8
#define CH    128
#define NPIX  4096
#define BR    128
#define BC    64
#define NT    (NPIX / BC)   // 64
#define JSPLIT 4
#define TILES_PER_UNIT (NT / JSPLIT)   // 16

// bf16 hi/lo split operands (S-phase emulated-fp32 MMA)
__device__ __align__(16) __nv_bfloat16 g_Qhi[BATCH * NPIX * CH];  // [b][n][c]
__device__ __align__(16) __nv_bfloat16 g_Qlo[BATCH * NPIX * CH];
__device__ __align__(16) __nv_bfloat16 g_Khi[BATCH * NPIX * CH];  // [b][n][c]
__device__ __align__(16) __nv_bfloat16 g_Klo[BATCH * NPIX * CH];
// V in fp16 single precision level (PV is single-term fp16 MMA)
__device__ __align__(16) __half g_Vh[BATCH * CH * NPIX];          // [b][c][n]

// split-j partials: O [b][jc][iblk][i 128][c 128]; ML [unit][2][128] (m, l)
__device__ __align__(16) float g_O[BATCH * JSPLIT * 32 * 128 * 128];  // 64 MB
__device__ __align__(16) float g_ML[BATCH * JSPLIT * 32 * 256];

typedef unsigned long long u64;

__device__ __forceinline__ uint32_t smem_u32(const void* p) {
    uint32_t a;
    asm("{ .reg .u64 t; cvta.to.shared.u64 t, %1; cvt.u32.u64 %0, t; }" : "=r"(a) : "l"(p));
    return a;
}
__device__ __forceinline__ void cpasync16(uint32_t dst, const void* src) {
    asm volatile("cp.async.cg.shared.global [%0], [%1], 16;" :: "r"(dst), "l"(src));
}
#define CP_COMMIT() asm volatile("cp.async.commit_group;" ::: "memory")
#define CP_WAIT0()  asm volatile("cp.async.wait_group 0;" ::: "memory")

__device__ __forceinline__ float ex2(float x) {
    float y; asm("ex2.approx.ftz.f32 %0, %1;" : "=f"(y) : "f"(x)); return y;
}

// m16n8k16 row.col bf16 -> fp32, D==C in place
__device__ __forceinline__ void mma16816(float* c,
    uint32_t a0, uint32_t a1, uint32_t a2, uint32_t a3, uint32_t b0, uint32_t b1) {
    asm volatile(
        "mma.sync.aligned.m16n8k16.row.col.f32.bf16.bf16.f32 "
        "{%0,%1,%2,%3}, {%4,%5,%6,%7}, {%8,%9}, {%0,%1,%2,%3};"
        : "+f"(c[0]), "+f"(c[1]), "+f"(c[2]), "+f"(c[3])
        : "r"(a0), "r"(a1), "r"(a2), "r"(a3), "r"(b0), "r"(b1));
}
// fp16 variant
__device__ __forceinline__ void mma16816h(float* c,
    uint32_t a0, uint32_t a1, uint32_t a2, uint32_t a3, uint32_t b0, uint32_t b1) {
    asm volatile(
        "mma.sync.aligned.m16n8k16.row.col.f32.f16.f16.f32 "
        "{%0,%1,%2,%3}, {%4,%5,%6,%7}, {%8,%9}, {%0,%1,%2,%3};"
        : "+f"(c[0]), "+f"(c[1]), "+f"(c[2]), "+f"(c[3])
        : "r"(a0), "r"(a1), "r"(a2), "r"(a3), "r"(b0), "r"(b1));
}

__device__ __forceinline__ void ldsm4(uint32_t& r0, uint32_t& r1, uint32_t& r2,
                                      uint32_t& r3, uint32_t addr) {
    asm volatile("ldmatrix.sync.aligned.m8n8.x4.shared.b16 {%0,%1,%2,%3}, [%4];"
                 : "=r"(r0), "=r"(r1), "=r"(r2), "=r"(r3) : "r"(addr));
}
__device__ __forceinline__ void ldsm4t(uint32_t& r0, uint32_t& r1, uint32_t& r2,
                                       uint32_t& r3, uint32_t addr) {
    asm volatile("ldmatrix.sync.aligned.m8n8.x4.trans.shared.b16 {%0,%1,%2,%3}, [%4];"
                 : "=r"(r0), "=r"(r1), "=r"(r2), "=r"(r3) : "r"(addr));
}

__device__ __forceinline__ uint32_t f16pack(float pe, float po) {
    uint32_t r;
    asm("cvt.rn.f16x2.f32 %0, %1, %2;" : "=r"(r) : "f"(po), "f"(pe));
    return r;
}
__device__ __forceinline__ void split2(float a, float b, uint32_t& hi, uint32_t& lo) {
    __nv_bfloat162 h = __floats2bfloat162_rn(a, b);
    float2 hf = __bfloat1622float2(h);
    __nv_bfloat162 l = __floats2bfloat162_rn(a - hf.x, b - hf.y);
    union { __nv_bfloat162 v; uint32_t u; } ch, cl;
    ch.v = h; cl.v = l;
    hi = ch.u; lo = cl.u;
}

#define LOG2E 1.4426950408889634f

// ====== QKV projection on HMMA bf16x3 ======
#define WHI_B 0
#define WLO_B 34816
#define XHI_B 69632
#define XLO_B 104448
#define PROJ_SMEM_BYTES 139264

__global__ void __launch_bounds__(256, 1) qkv_kernel(
    const float* __restrict__ x1, const float* __restrict__ x2,
    const float* __restrict__ Wq, const float* __restrict__ bq,
    const float* __restrict__ Wk, const float* __restrict__ bk,
    const float* __restrict__ Wv, const float* __restrict__ bv)
{
    extern __shared__ __align__(16) char smc[];
    const uint32_t sb = smem_u32(smc);

    const int t = threadIdx.x;
    const int wid = t >> 5;
    const int lane = t & 31;
    const int l7 = lane & 7;
    const int r8 = lane >> 3;
    const bool isQ = (blockIdx.y == 0);
    const int b = blockIdx.z, p0 = blockIdx.x * 128;

    const float* X = (isQ ? x1 : x2) + (size_t)b * CH * NPIX;

#pragma unroll
    for (int r = 0; r < 16; ++r) {
        int idx = t + 256 * r;
        int c = idx >> 5, p4 = (idx & 31) * 4;
        float4 x4 = *(const float4*)&X[(size_t)c * NPIX + p0 + p4];
        uint32_t h0, l0, h1, l1;
        split2(x4.x, x4.y, h0, l0);
        split2(x4.z, x4.w, h1, l1);
        *(uint2*)(smc + XHI_B + c * 272 + p4 * 2) = make_uint2(h0, h1);
        *(uint2*)(smc + XLO_B + c * 272 + p4 * 2) = make_uint2(l0, l1);
    }

    const int g = lane >> 2, q4 = lane & 3;
    const int npass = isQ ? 1 : 2;

    for (int pass = 0; pass < npass; ++pass) {
        const float* W    = isQ ? Wq : (pass == 0 ? Wk : Wv);
        const float* bias = isQ ? bq : (pass == 0 ? bk : bv);
        if (pass) __syncthreads();

#pragma unroll
        for (int r = 0; r < 4; ++r) {
            int task = t + 256 * r;
            int o = task >> 3, c16 = (task & 7) * 16;
            const float4* ws = (const float4*)&W[o * CH + c16];
            uint32_t hi[8], lo[8];
#pragma unroll
            for (int j = 0; j < 4; ++j) {
                float4 w4 = ws[j];
                split2(w4.x, w4.y, hi[2 * j], lo[2 * j]);
                split2(w4.z, w4.w, hi[2 * j + 1], lo[2 * j + 1]);
            }
            char* dh = smc + WHI_B + o * 272 + c16 * 2;
            char* dl = smc + WLO_B + o * 272 + c16 * 2;
            ((uint4*)dh)[0] = make_uint4(hi[0], hi[1], hi[2], hi[3]);
            ((uint4*)dh)[1] = make_uint4(hi[4], hi[5], hi[6], hi[7]);
            ((uint4*)dl)[0] = make_uint4(lo[0], lo[1], lo[2], lo[3]);
            ((uint4*)dl)[1] = make_uint4(lo[4], lo[5], lo[6], lo[7]);
        }
        __syncthreads();

        float acc[16][4];
#pragma unroll
        for (int n = 0; n < 16; ++n)
#pragma unroll
            for (int r = 0; r < 4; ++r) acc[n][r] = 0.f;

        if (isQ || pass == 0) {
            const uint32_t aT = sb + XHI_B
                + (uint32_t)((r8 & 1) * 8 + l7) * 272
                + (uint32_t)(wid * 16 + (r8 >> 1) * 8) * 2;
            const uint32_t bW = sb + WHI_B
                + (uint32_t)((r8 >> 1) * 8 + l7) * 272 + (uint32_t)(r8 & 1) * 16;
#pragma unroll
            for (int kk = 0; kk < 8; ++kk) {
                uint32_t a0h, a1h, a2h, a3h, a0l, a1l, a2l, a3l;
                ldsm4t(a0h, a2h, a1h, a3h, aT + kk * 16 * 272);
                ldsm4t(a0l, a2l, a1l, a3l, aT + (XLO_B - XHI_B) + kk * 16 * 272);
#pragma unroll
                for (int np = 0; np < 8; ++np) {
                    uint32_t b00, b01, b10, b11, c00, c01, c10, c11;
                    ldsm4(b00, b01, b10, b11, bW + np * 4352 + kk * 32);
                    ldsm4(c00, c01, c10, c11, bW + (WLO_B - WHI_B) + np * 4352 + kk * 32);
                    mma16816(acc[2 * np],     a0h, a1h, a2h, a3h, b00, b01);
                    mma16816(acc[2 * np],     a0l, a1l, a2l, a3l, b00, b01);
                    mma16816(acc[2 * np],     a0h, a1h, a2h, a3h, c00, c01);
                    mma16816(acc[2 * np + 1], a0h, a1h, a2h, a3h, b10, b11);
                    mma16816(acc[2 * np + 1], a0l, a1l, a2l, a3l, b10, b11);
                    mma16816(acc[2 * np + 1], a0h, a1h, a2h, a3h, c10, c11);
                }
            }
            const float qsc = isQ ? LOG2E : 1.0f;
            __nv_bfloat16* dHi = isQ ? g_Qhi : g_Khi;
            __nv_bfloat16* dLo = isQ ? g_Qlo : g_Klo;
            const int p = wid * 16 + g;
            size_t r0 = ((size_t)b * NPIX + p0 + p) * CH;
            size_t r8b = r0 + (size_t)8 * CH;
#pragma unroll
            for (int n = 0; n < 16; ++n) {
                const int o = n * 8 + 2 * q4;
                float2 bo = *(const float2*)&bias[o];
                uint32_t h0, l0, h1, l1;
                split2((acc[n][0] + bo.x) * qsc, (acc[n][1] + bo.y) * qsc, h0, l0);
                split2((acc[n][2] + bo.x) * qsc, (acc[n][3] + bo.y) * qsc, h1, l1);
                *(uint32_t*)(dHi + r0 + o)  = h0;
                *(uint32_t*)(dLo + r0 + o)  = l0;
                *(uint32_t*)(dHi + r8b + o) = h1;
                *(uint32_t*)(dLo + r8b + o) = l1;
            }
        } else {
            const uint32_t aH = sb + WHI_B
                + (uint32_t)(wid * 16 + l7 + (r8 & 1) * 8) * 272
                + (uint32_t)((lane >> 4) & 1) * 16;
            const uint32_t aL = aH + (WLO_B - WHI_B);
            const uint32_t bT = sb + XHI_B
                + (uint32_t)((r8 & 1) * 8 + l7) * 272 + (uint32_t)(r8 >> 1) * 16;
#pragma unroll
            for (int kk = 0; kk < 8; ++kk) {
                uint32_t a0h, a1h, a2h, a3h, a0l, a1l, a2l, a3l;
                ldsm4(a0h, a1h, a2h, a3h, aH + kk * 32);
                ldsm4(a0l, a1l, a2l, a3l, aL + kk * 32);
                const uint32_t bk16 = bT + (uint32_t)kk * 16 * 272;
#pragma unroll
                for (int np = 0; np < 8; ++np) {
                    uint32_t b00, b01, b10, b11, c00, c01, c10, c11;
                    ldsm4t(b00, b01, b10, b11, bk16 + np * 32);
                    ldsm4t(c00, c01, c10, c11, bk16 + (XLO_B - XHI_B) + np * 32);
                    mma16816(acc[2 * np],     a0h, a1h, a2h, a3h, b00, b01);
                    mma16816(acc[2 * np],     a0l, a1l, a2l, a3l, b00, b01);
                    mma16816(acc[2 * np],     a0h, a1h, a2h, a3h, c00, c01);
                    mma16816(acc[2 * np + 1], a0h, a1h, a2h, a3h, b10, b11);
                    mma16816(acc[2 * np + 1], a0l, a1l, a2l, a3l, b10, b11);
                    mma16816(acc[2 * np + 1], a0h, a1h, a2h, a3h, c10, c11);
                }
            }
            // V epilogue: fp16 single, [o][p]
            const int o0 = wid * 16 + g;
            float bo0 = bv[o0], bo8 = bv[o0 + 8];
            size_t rb0 = ((size_t)b * CH + o0) * NPIX + p0;
            size_t rb8 = rb0 + (size_t)8 * NPIX;
#pragma unroll
            for (int n = 0; n < 16; ++n) {
                const int p = n * 8 + 2 * q4;
                *(uint32_t*)(g_Vh + rb0 + p) = f16pack(acc[n][0] + bo0, acc[n][1] + bo0);
                *(uint32_t*)(g_Vh + rb8 + p) = f16pack(acc[n][2] + bo8, acc[n][3] + bo8);
            }
        }
    }
}

// ==== flash attention partial: bf16x3 S + fp16 PV with running row-max ====
#define QHI_B 0
#define QLO_B 34816
#define BUF_B 69632
#define BUFSTRIDE 53248   // Khi 17408 + Klo 17408 + Vh 18432
#define KHI_B(d) (BUF_B + (d) * BUFSTRIDE)
#define VH_B(d)  (KHI_B(d) + 2 * 17408)
#define ATTN_SMEM_BYTES (BUF_B + 2 * BUFSTRIDE)   // 176128

__global__ void __launch_bounds__(256, 1) attn_kernel()
{
    extern __shared__ __align__(16) uint32_t sm32[];
    const uint32_t sb = smem_u32(sm32);

    const int t = threadIdx.x;
    const int wid = t >> 5;
    const int lane = t & 31;
    const int l7 = lane & 7;
    const int r8 = lane >> 3;
    const int iblk = blockIdx.x;
    const int jc   = blockIdx.y;
    const int b    = blockIdx.z;
    const int i0 = iblk * BR;
    const int jt0 = jc * TILES_PER_UNIT;

    {
        const char* qh = (const char*)(g_Qhi + ((size_t)b * NPIX + i0) * CH);
        const char* ql = (const char*)(g_Qlo + ((size_t)b * NPIX + i0) * CH);
#pragma unroll
        for (int r = 0; r < 8; ++r) {
            int idx = t + 256 * r;
            int row = idx >> 4, off = idx & 15;
            cpasync16(sb + QHI_B + row * 272 + off * 16, qh + (size_t)idx * 16);
            cpasync16(sb + QLO_B + row * 272 + off * 16, ql + (size_t)idx * 16);
        }
        const int j0 = jt0 * BC;
        const char* kh = (const char*)(g_Khi + ((size_t)b * NPIX + j0) * CH);
        const char* kl = (const char*)(g_Klo + ((size_t)b * NPIX + j0) * CH);
        const char* vh = (const char*)(g_Vh + (size_t)b * CH * NPIX + j0);
#pragma unroll
        for (int r = 0; r < 4; ++r) {
            int idx = t + 256 * r;
            int row = idx >> 4, off = idx & 15;
            cpasync16(sb + KHI_B(0) + row * 272 + off * 16, kh + (size_t)idx * 16);
            cpasync16(sb + KHI_B(0) + 17408 + row * 272 + off * 16, kl + (size_t)idx * 16);
        }
#pragma unroll
        for (int r = 0; r < 4; ++r) {
            int idx = t + 256 * r;
            int row = idx >> 3, off = idx & 7;
            cpasync16(sb + VH_B(0) + row * 144 + off * 16,
                      vh + (size_t)row * NPIX * 2 + off * 16);
        }
        CP_COMMIT();
    }

    float o[16][4];
#pragma unroll
    for (int n = 0; n < 16; ++n)
#pragma unroll
        for (int r = 0; r < 4; ++r) o[n][r] = 0.f;
    float lsum0 = 0.f, lsum1 = 0.f;
    float m0 = -INFINITY, m1 = -INFINITY;

    const uint32_t aOffH = sb + QHI_B
        + (uint32_t)(wid * 16 + l7 + (r8 & 1) * 8) * 272 + (uint32_t)((lane >> 4) & 1) * 16;
    const uint32_t aOffL = aOffH + (QLO_B - QHI_B);
    const uint32_t bRow = (uint32_t)((r8 >> 1) * 8 + l7);
    const uint32_t bOffK = bRow * 272 + (uint32_t)(r8 & 1) * 16;
    const uint32_t bOffV = bRow * 144 + (uint32_t)(r8 & 1) * 16;

    for (int jt = jt0; jt < jt0 + TILES_PER_UNIT; ++jt) {
        const int d = jt & 1;
        CP_WAIT0();
        __syncthreads();

        if (jt + 1 < jt0 + TILES_PER_UNIT) {
            const int j0n = (jt + 1) * BC, dn = (jt + 1) & 1;
            const char* kh = (const char*)(g_Khi + ((size_t)b * NPIX + j0n) * CH);
            const char* kl = (const char*)(g_Klo + ((size_t)b * NPIX + j0n) * CH);
            const char* vh = (const char*)(g_Vh + (size_t)b * CH * NPIX + j0n);
#pragma unroll
            for (int r = 0; r < 4; ++r) {
                int idx = t + 256 * r;
                int row = idx >> 4, off = idx & 15;
                cpasync16(sb + KHI_B(dn) + row * 272 + off * 16, kh + (size_t)idx * 16);
                cpasync16(sb + KHI_B(dn) + 17408 + row * 272 + off * 16, kl + (size_t)idx * 16);
            }
#pragma unroll
            for (int r = 0; r < 4; ++r) {
                int idx = t + 256 * r;
                int row = idx >> 3, off = idx & 7;
                cpasync16(sb + VH_B(dn) + row * 144 + off * 16,
                          vh + (size_t)row * NPIX * 2 + off * 16);
            }
            CP_COMMIT();
        }

        // ---- S = Q K^T (3-term bf16) ----
        float s[8][4];
#pragma unroll
        for (int n = 0; n < 8; ++n)
#pragma unroll
            for (int r = 0; r < 4; ++r) s[n][r] = 0.f;

        const uint32_t kBase = sb + KHI_B(d) + bOffK;
#pragma unroll
        for (int kk = 0; kk < 8; ++kk) {
            uint32_t a0h, a1h, a2h, a3h, a0l, a1l, a2l, a3l;
            ldsm4(a0h, a1h, a2h, a3h, aOffH + kk * 32);
            ldsm4(a0l, a1l, a2l, a3l, aOffL + kk * 32);
#pragma unroll
            for (int np = 0; np < 4; ++np) {
                uint32_t b00, b01, b10, b11, c00, c01, c10, c11;
                ldsm4(b00, b01, b10, b11, kBase + np * 4352 + kk * 32);
                ldsm4(c00, c01, c10, c11, kBase + 17408 + np * 4352 + kk * 32);
                mma16816(s[2 * np],     a0h, a1h, a2h, a3h, b00, b01);
                mma16816(s[2 * np],     a0l, a1l, a2l, a3l, b00, b01);
                mma16816(s[2 * np],     a0h, a1h, a2h, a3h, c00, c01);
                mma16816(s[2 * np + 1], a0h, a1h, a2h, a3h, b10, b11);
                mma16816(s[2 * np + 1], a0l, a1l, a2l, a3l, b10, b11);
                mma16816(s[2 * np + 1], a0h, a1h, a2h, a3h, c10, c11);
            }
        }

        // ---- running row-max, rescale, exp2, sums ----
        {
            float mx0 = s[0][0], mx1 = s[0][2];
#pragma unroll
            for (int n = 0; n < 8; ++n) {
                mx0 = fmaxf(mx0, fmaxf(s[n][0], s[n][1]));
                mx1 = fmaxf(mx1, fmaxf(s[n][2], s[n][3]));
            }
            mx0 = fmaxf(mx0, __shfl_xor_sync(0xffffffffu, mx0, 1));
            mx0 = fmaxf(mx0, __shfl_xor_sync(0xffffffffu, mx0, 2));
            mx1 = fmaxf(mx1, __shfl_xor_sync(0xffffffffu, mx1, 1));
            mx1 = fmaxf(mx1, __shfl_xor_sync(0xffffffffu, mx1, 2));
            float m0n = fmaxf(m0, mx0), m1n = fmaxf(m1, mx1);
            float sc0 = ex2(m0 - m0n), sc1 = ex2(m1 - m1n);
            m0 = m0n; m1 = m1n;
            lsum0 *= sc0; lsum1 *= sc1;
#pragma unroll
            for (int n = 0; n < 8; ++n) {
                s[n][0] = ex2(s[n][0] - m0n);
                s[n][1] = ex2(s[n][1] - m0n);
                s[n][2] = ex2(s[n][2] - m1n);
                s[n][3] = ex2(s[n][3] - m1n);
                lsum0 += s[n][0] + s[n][1];
                lsum1 += s[n][2] + s[n][3];
            }
#pragma unroll
            for (int n = 0; n < 16; ++n) {
                o[n][0] *= sc0; o[n][1] *= sc0;
                o[n][2] *= sc1; o[n][3] *= sc1;
            }
        }

        // ---- O += P V : single-term fp16 ----
        const uint32_t vBase = sb + VH_B(d) + bOffV;
#pragma unroll
        for (int kk = 0; kk < 4; ++kk) {
            uint32_t pa0 = f16pack(s[2 * kk][0],     s[2 * kk][1]);
            uint32_t pa1 = f16pack(s[2 * kk][2],     s[2 * kk][3]);
            uint32_t pa2 = f16pack(s[2 * kk + 1][0], s[2 * kk + 1][1]);
            uint32_t pa3 = f16pack(s[2 * kk + 1][2], s[2 * kk + 1][3]);
#pragma unroll
            for (int n2 = 0; n2 < 8; ++n2) {
                uint32_t b00, b01, b10, b11;
                ldsm4(b00, b01, b10, b11, vBase + n2 * 2304 + kk * 32);
                mma16816h(o[2 * n2],     pa0, pa1, pa2, pa3, b00, b01);
                mma16816h(o[2 * n2 + 1], pa0, pa1, pa2, pa3, b10, b11);
            }
        }
        __syncthreads();
    }

    lsum0 += __shfl_xor_sync(0xffffffffu, lsum0, 1);
    lsum0 += __shfl_xor_sync(0xffffffffu, lsum0, 2);
    lsum1 += __shfl_xor_sync(0xffffffffu, lsum1, 1);
    lsum1 += __shfl_xor_sync(0xffffffffu, lsum1, 2);

    const size_t unit = ((size_t)(b * JSPLIT + jc) * 32 + iblk);
    float* Ob = g_O + unit * (128 * 128);
    float* ML = g_ML + unit * 256;
    const int g = lane >> 2, q = lane & 3;
    const int i = wid * 16 + g;
    if ((lane & 3) == 0) {
        ML[i]           = m0;
        ML[i + 8]       = m1;
        ML[128 + i]     = lsum0;
        ML[128 + i + 8] = lsum1;
    }
#pragma unroll
    for (int n = 0; n < 16; ++n) {
        const int c = n * 8 + 2 * q;
        *(float2*)&Ob[(size_t)i * 128 + c]       = make_float2(o[n][0], o[n][1]);
        *(float2*)&Ob[(size_t)(i + 8) * 128 + c] = make_float2(o[n][2], o[n][3]);
    }
}

// ==== merge: max-combine 4 j-chunk partials, normalize, transpose, store ====
#define MERGE_SMEM_BYTES (128 * 129 * 4 + 128 * 4 + 4 * 128 * 4)   // 68608

__global__ void __launch_bounds__(256, 1) merge_kernel(float* __restrict__ out)
{
    extern __shared__ __align__(16) float ms[];
    float* Os   = ms;                       // [c:128][i:129]
    float* Linv = ms + 128 * 129;           // [128]
    float* F    = ms + 128 * 129 + 128;     // [4][128] chunk rescale factors

    const int t = threadIdx.x;
    const int iblk = blockIdx.x;
    const int b    = blockIdx.y;

    const float* O0 = g_O + ((size_t)(b * JSPLIT) * 32 + iblk) * (128 * 128);
    const size_t sj = (size_t)32 * 128 * 128;

    if (t < 128) {
        const size_t u0 = ((size_t)(b * JSPLIT) * 32 + iblk) * 256;
        const size_t uj = (size_t)32 * 256;
        float m[4], l[4];
#pragma unroll
        for (int c = 0; c < 4; ++c) {
            m[c] = g_ML[u0 + c * uj + t];
            l[c] = g_ML[u0 + c * uj + 128 + t];
        }
        float M = fmaxf(fmaxf(m[0], m[1]), fmaxf(m[2], m[3]));
        float L = 0.f;
#pragma unroll
        for (int c = 0; c < 4; ++c) {
            float f = ex2(m[c] - M);
            F[c * 128 + t] = f;
            L += l[c] * f;
        }
        Linv[t] = 1.f / L;
    }
    __syncthreads();

#pragma unroll
    for (int r = 0; r < 16; ++r) {
        int idx = (r * 256 + t) * 4;
        int i = idx >> 7, c = idx & 127;
        float f0 = F[i], f1 = F[128 + i], f2 = F[256 + i], f3 = F[384 + i];
        float4 a  = *(const float4*)&O0[idx];
        float4 b2 = *(const float4*)&O0[sj + idx];
        float4 c4 = *(const float4*)&O0[2 * sj + idx];
        float4 d4 = *(const float4*)&O0[3 * sj + idx];
        Os[(c + 0) * 129 + i] = a.x * f0 + b2.x * f1 + c4.x * f2 + d4.x * f3;
        Os[(c + 1) * 129 + i] = a.y * f0 + b2.y * f1 + c4.y * f2 + d4.y * f3;
        Os[(c + 2) * 129 + i] = a.z * f0 + b2.z * f1 + c4.z * f2 + d4.z * f3;
        Os[(c + 3) * 129 + i] = a.w * f0 + b2.w * f1 + c4.w * f2 + d4.w * f3;
    }
    __syncthreads();

    const int c = t >> 1, h = t & 1;
    const float* src = Os + c * 129 + 64 * h;
    const float* li  = Linv + 64 * h;
    float* dst = out + ((size_t)b * CH + c) * NPIX + iblk * 128 + 64 * h;
#pragma unroll
    for (int k = 0; k < 16; ++k) {
        ((float4*)dst)[k] = make_float4(src[4 * k]     * li[4 * k],
                                        src[4 * k + 1] * li[4 * k + 1],
                                        src[4 * k + 2] * li[4 * k + 2],
                                        src[4 * k + 3] * li[4 * k + 3]);
    }
}

// ============================================================
extern "C" void kernel_launch(void* const* d_in, const int* in_sizes, int n_in,
                              void* d_out, int out_size)
{
    (void)in_sizes; (void)n_in; (void)out_size;
    const float* x1 = (const float*)d_in[0];
    const float* x2 = (const float*)d_in[1];
    const float* Wq = (const float*)d_in[2];
    const float* bq = (const float*)d_in[3];
    const float* Wk = (const float*)d_in[4];
    const float* bk = (const float*)d_in[5];
    const float* Wv = (const float*)d_in[6];
    const float* bv = (const float*)d_in[7];
    float* out = (float*)d_out;

    cudaFuncSetAttribute(qkv_kernel, cudaFuncAttributeMaxDynamicSharedMemorySize, PROJ_SMEM_BYTES);
    cudaFuncSetAttribute(attn_kernel, cudaFuncAttributeMaxDynamicSharedMemorySize, ATTN_SMEM_BYTES);
    cudaFuncSetAttribute(merge_kernel, cudaFuncAttributeMaxDynamicSharedMemorySize, MERGE_SMEM_BYTES);

    qkv_kernel<<<dim3(NPIX / 128, 2, BATCH), 256, PROJ_SMEM_BYTES>>>(x1, x2, Wq, bq, Wk, bk, Wv, bv);
    attn_kernel<<<dim3(NPIX / BR, JSPLIT, BATCH), 256, ATTN_SMEM_BYTES>>>();
    merge_kernel<<<dim3(NPIX / 128, BATCH), 256, MERGE_SMEM_BYTES>>>(out);
}